// round 11
// baseline (speedup 1.0000x reference)
#include <cuda_runtime.h>
#include <cuda_bf16.h>
#include <cstdint>
#include <math.h>

#define BATCH 8
#define SEQ   2048
#define DA    768
#define DB    1024

// ---------------- scratch (device globals; module-load allocation) ---------
__device__ float g_s   [BATCH * SEQ * SEQ];            // fp32 scores
__device__ float g_xb2 [BATCH * SEQ * DB];             // fp32 residual
// bf16 hi/lo pairs
__device__ __nv_bfloat16 g_xbh[BATCH * SEQ * DB],  g_xbl[BATCH * SEQ * DB];
__device__ __nv_bfloat16 g_xah[BATCH * SEQ * DA],  g_xal[BATCH * SEQ * DA];
__device__ __nv_bfloat16 g_qh [BATCH * SEQ * DB],  g_ql [BATCH * SEQ * DB];
__device__ __nv_bfloat16 g_kh [BATCH * SEQ * DB],  g_kl [BATCH * SEQ * DB];
__device__ __nv_bfloat16 g_vh [BATCH * SEQ * DB],  g_vl [BATCH * SEQ * DB];
__device__ __nv_bfloat16 g_vth[BATCH * SEQ * DB],  g_vtl[BATCH * SEQ * DB];
__device__ __nv_bfloat16 g_ph [BATCH * SEQ * SEQ], g_pl [BATCH * SEQ * SEQ];
__device__ __nv_bfloat16 g_x2h[BATCH * SEQ * DB],  g_x2l[BATCH * SEQ * DB];
__device__ __nv_bfloat16 g_ath[BATCH * SEQ * DB],  g_atl[BATCH * SEQ * DB];
__device__ __nv_bfloat16 g_wth[8 * DB * DB],       g_wtl[8 * DB * DB];

// ---------------- helpers ---------------------------------------------------
__device__ __forceinline__ void split_bf16(float x, __nv_bfloat16& h, __nv_bfloat16& l) {
    h = __float2bfloat16_rn(x);
    l = __float2bfloat16_rn(x - __bfloat162float(h));
}
__device__ __forceinline__ uint32_t pack2(__nv_bfloat16 a, __nv_bfloat16 b) {
    __nv_bfloat162 t; t.x = a; t.y = b;
    return *(uint32_t*)&t;
}
__device__ __forceinline__ uint32_t smem_u32(const void* p) {
    uint32_t a;
    asm("{ .reg .u64 t; cvta.to.shared.u64 t, %1; cvt.u32.u64 %0, t; }"
        : "=r"(a) : "l"(p));
    return a;
}
__device__ __forceinline__ void cp16(uint32_t dst, const void* src) {
    asm volatile("cp.async.cg.shared.global [%0], [%1], 16;"
                 :: "r"(dst), "l"(src));
}
#define CP_COMMIT() asm volatile("cp.async.commit_group;")
#define CP_WAIT(n)  asm volatile("cp.async.wait_group %0;" :: "n"(n))

#define MMA_BF16(acc, Af, Bf)                                                  \
    asm volatile(                                                              \
        "mma.sync.aligned.m16n8k16.row.col.f32.bf16.bf16.f32 "                 \
        "{%0,%1,%2,%3},{%4,%5,%6,%7},{%8,%9},{%0,%1,%2,%3};"                   \
        : "+f"((acc)[0]), "+f"((acc)[1]), "+f"((acc)[2]), "+f"((acc)[3])       \
        : "r"((Af)[0]), "r"((Af)[1]), "r"((Af)[2]), "r"((Af)[3]),              \
          "r"((Bf)[0]), "r"((Bf)[1]))

#define LDSM4(r0, r1, r2, r3, a)                                               \
    asm volatile("ldmatrix.sync.aligned.m8n8.x4.shared.b16 {%0,%1,%2,%3}, [%4];" \
        : "=r"(r0), "=r"(r1), "=r"(r2), "=r"(r3) : "r"(a))

// ---------------------------------------------------------------------------
// mma.sync GEMM on pre-split bf16 operands (3-pass hi/lo compensation):
//   C = alpha * A @ B^T [+ bias] [+ res];  A:[M,K], B:[N,K], both as (h,l).
//   CTA 128x128, K-chunk 32, cp.async double-buffer, ldmatrix fragments.
//   8 warps as 2(M)x4(N), warp tile 64x32, m16n8k16.
// SMEM stage: 4 arrays x [128 rows x 80B] (64B data + 16B pad). 2 stages.
// ---------------------------------------------------------------------------
#define ROWB 80
#define ARR_BYTES (128 * ROWB)          // 10240
#define OFF_AL (1 * ARR_BYTES)
#define OFF_BH (2 * ARR_BYTES)
#define OFF_BL (3 * ARR_BYTES)
#define STAGE  (4 * ARR_BYTES)          // 40960
#define SMEM_DYN (2 * STAGE)            // 81920

template<bool HAS_BIAS, bool HAS_RES, bool WRITE_F32, bool WRITE_SPLIT>
__global__ __launch_bounds__(256)
void mma_gemm(const __nv_bfloat16* __restrict__ Ah, const __nv_bfloat16* __restrict__ Al,
              const __nv_bfloat16* __restrict__ Bh, const __nv_bfloat16* __restrict__ Bl,
              const float* __restrict__ bias, const float* __restrict__ res,
              float* __restrict__ C, __nv_bfloat16* __restrict__ Ch,
              __nv_bfloat16* __restrict__ Cl,
              int M, int N, int K, float alpha,
              size_t sA, size_t sB, size_t sC)
{
    extern __shared__ char smem[];
    const uint32_t sb = smem_u32(smem);

    const int bz = blockIdx.z;
    Ah += (size_t)bz * sA; Al += (size_t)bz * sA;
    Bh += (size_t)bz * sB; Bl += (size_t)bz * sB;
    const size_t cOff = (size_t)bz * sC;

    const int row0 = blockIdx.y * 128;
    const int col0 = blockIdx.x * 128;
    const int tid  = threadIdx.x;
    const int wid  = tid >> 5;
    const int lane = tid & 31;
    const int wm   = wid >> 2;          // 0..1  (M)
    const int wn   = wid & 3;           // 0..3  (N)
    const int lr   = lane >> 2;         // 0..7
    const int lc   = lane & 3;          // 0..3

    // cp.async source/dest mapping: 512 slots of 16B per array per stage
    const int f0r = tid >> 2;           // row 0..63 (i=0), +64 for i=1
    const int f0c = tid & 3;            // 16B col (0..3) within 64B row data
    // ldmatrix lane addressing
    const int g  = lane >> 3, ri = lane & 7;
    const int aR = (g & 1) * 8 + ri;    // A: row-in-16, col16 = (g>>1)*16
    const int aC = (g >> 1) * 16;
    const int bR = (g >> 1) * 8 + ri;   // B: row-in-16, col16 = (g&1)*16
    const int bC = (g & 1) * 16;

    float acc[4][4][4];
    #pragma unroll
    for (int a = 0; a < 4; a++)
        #pragma unroll
        for (int b = 0; b < 4; b++)
            #pragma unroll
            for (int c = 0; c < 4; c++)
                acc[a][b][c] = 0.0f;

    const int nCh = K / 32;

    // ---- stage loader (8 x cp.async.16 per thread) ----
    auto load_stage = [&](int st, int ch) {
        const uint32_t base = sb + st * STAGE;
        #pragma unroll
        for (int i = 0; i < 2; i++) {
            int r = f0r + i * 64;
            uint32_t d = r * ROWB + f0c * 16;
            size_t oa = (size_t)(row0 + r) * K + ch * 32 + f0c * 8;
            size_t ob = (size_t)(col0 + r) * K + ch * 32 + f0c * 8;
            cp16(base + d,          Ah + oa);
            cp16(base + OFF_AL + d, Al + oa);
            cp16(base + OFF_BH + d, Bh + ob);
            cp16(base + OFF_BL + d, Bl + ob);
        }
        CP_COMMIT();
    };

    load_stage(0, 0);

    for (int ch = 0; ch < nCh; ch++) {
        if (ch + 1 < nCh) { load_stage((ch + 1) & 1, ch + 1); CP_WAIT(1); }
        else              { CP_WAIT(0); }
        __syncthreads();

        const uint32_t base = sb + (ch & 1) * STAGE;
        #pragma unroll
        for (int s = 0; s < 2; s++) {
            uint32_t Afh[4][4], Afl[4][4], Bfh[4][2], Bfl[4][2];
            #pragma unroll
            for (int mt = 0; mt < 4; mt++) {
                uint32_t ar = base + (wm * 64 + mt * 16 + aR) * ROWB + s * 32 + aC;
                LDSM4(Afh[mt][0], Afh[mt][1], Afh[mt][2], Afh[mt][3], ar);
                LDSM4(Afl[mt][0], Afl[mt][1], Afl[mt][2], Afl[mt][3], ar + OFF_AL);
            }
            #pragma unroll
            for (int np = 0; np < 2; np++) {
                uint32_t br = base + OFF_BH + (wn * 32 + np * 16 + bR) * ROWB + s * 32 + bC;
                LDSM4(Bfh[2*np][0], Bfh[2*np][1], Bfh[2*np+1][0], Bfh[2*np+1][1], br);
                LDSM4(Bfl[2*np][0], Bfl[2*np][1], Bfl[2*np+1][0], Bfl[2*np+1][1],
                      br + (OFF_BL - OFF_BH));
            }
            #pragma unroll
            for (int mt = 0; mt < 4; mt++)
                #pragma unroll
                for (int nt = 0; nt < 4; nt++) {
                    MMA_BF16(acc[mt][nt], Afh[mt], Bfh[nt]);
                    MMA_BF16(acc[mt][nt], Afh[mt], Bfl[nt]);
                    MMA_BF16(acc[mt][nt], Afl[mt], Bfh[nt]);
                }
        }
        __syncthreads();
    }

    // ---- epilogue ----
    const float* __restrict__ R = HAS_RES ? (res + cOff) : nullptr;
    #pragma unroll
    for (int mt = 0; mt < 4; mt++) {
        #pragma unroll
        for (int nt = 0; nt < 4; nt++) {
            int r = row0 + wm * 64 + mt * 16 + lr;
            int c = col0 + wn * 32 + nt * 8 + lc * 2;
            float2 o0, o1;
            o0.x = acc[mt][nt][0] * alpha; o0.y = acc[mt][nt][1] * alpha;
            o1.x = acc[mt][nt][2] * alpha; o1.y = acc[mt][nt][3] * alpha;
            if (HAS_BIAS) {
                float2 bv = *(const float2*)&bias[c];
                o0.x += bv.x; o0.y += bv.y;
                o1.x += bv.x; o1.y += bv.y;
            }
            if (HAS_RES) {
                float2 r0 = *(const float2*)&R[(size_t)r * N + c];
                float2 r1 = *(const float2*)&R[(size_t)(r + 8) * N + c];
                o0.x += r0.x; o0.y += r0.y;
                o1.x += r1.x; o1.y += r1.y;
            }
            if (WRITE_F32) {
                *(float2*)&C[cOff + (size_t)r * N + c]       = o0;
                *(float2*)&C[cOff + (size_t)(r + 8) * N + c] = o1;
            }
            if (WRITE_SPLIT) {
                __nv_bfloat16 hx, lx, hy, ly;
                split_bf16(o0.x, hx, lx); split_bf16(o0.y, hy, ly);
                *(uint32_t*)&Ch[cOff + (size_t)r * N + c] = pack2(hx, hy);
                *(uint32_t*)&Cl[cOff + (size_t)r * N + c] = pack2(lx, ly);
                split_bf16(o1.x, hx, lx); split_bf16(o1.y, hy, ly);
                *(uint32_t*)&Ch[cOff + (size_t)(r + 8) * N + c] = pack2(hx, hy);
                *(uint32_t*)&Cl[cOff + (size_t)(r + 8) * N + c] = pack2(lx, ly);
            }
        }
    }
}

// ---------------------------------------------------------------------------
// Elementwise split: fp32 -> (hi, lo) bf16.
// ---------------------------------------------------------------------------
__global__ __launch_bounds__(256)
void split_kernel(const float* __restrict__ in, __nv_bfloat16* __restrict__ h,
                  __nv_bfloat16* __restrict__ l, size_t n4)
{
    size_t i = (size_t)blockIdx.x * 256 + threadIdx.x;
    if (i >= n4) return;
    float4 v = ((const float4*)in)[i];
    __nv_bfloat16 hx, lx, hy, ly, hz, lz, hw, lw;
    split_bf16(v.x, hx, lx); split_bf16(v.y, hy, ly);
    split_bf16(v.z, hz, lz); split_bf16(v.w, hw, lw);
    uint2 uh, ul;
    uh.x = pack2(hx, hy); uh.y = pack2(hz, hw);
    ul.x = pack2(lx, ly); ul.y = pack2(lz, lw);
    *(uint2*)&h[i * 4] = uh;
    *(uint2*)&l[i * 4] = ul;
}

// ---------------------------------------------------------------------------
// All-weights transpose+split in ONE launch (z = weight slot 0..7).
// in [rows][1024] fp32 -> (h,l) bf16 [1024][rows]; rows = 1024 (768 for z=4).
// ---------------------------------------------------------------------------
struct WPack {
    const float* src[8];
    __nv_bfloat16* h[8];
    __nv_bfloat16* l[8];
    int rows[8];
};

__global__ void transpose_split_all(WPack p)
{
    __shared__ float t[32][33];
    const int z = blockIdx.z;
    const int rows = p.rows[z];
    const int by = blockIdx.y * 32;
    if (by >= rows) return;
    const float* in = p.src[z];
    __nv_bfloat16* h = p.h[z];
    __nv_bfloat16* l = p.l[z];
    int bx = blockIdx.x * 32;
    int x = threadIdx.x, y = threadIdx.y;
    #pragma unroll
    for (int i = 0; i < 32; i += 8)
        t[y + i][x] = in[(size_t)(by + y + i) * DB + bx + x];
    __syncthreads();
    #pragma unroll
    for (int i = 0; i < 32; i += 8) {
        float v = t[x][y + i];
        __nv_bfloat16 hv, lv;
        split_bf16(v, hv, lv);
        size_t o = (size_t)(bx + y + i) * rows + by + x;
        h[o] = hv; l[o] = lv;
    }
}

// ---------------------------------------------------------------------------
// bf16 transpose (2-byte elements), batched over z.
// ---------------------------------------------------------------------------
__global__ void transpose16(const uint16_t* __restrict__ in,
                            uint16_t* __restrict__ outp, int rows, int cols)
{
    __shared__ uint16_t t[32][34];
    const size_t boff = (size_t)blockIdx.z * rows * cols;
    const uint16_t* ib = in + boff;
    uint16_t* ob = outp + boff;
    int bx = blockIdx.x * 32, by = blockIdx.y * 32;
    int x = threadIdx.x, y = threadIdx.y;
    #pragma unroll
    for (int i = 0; i < 32; i += 8)
        t[y + i][x] = ib[(size_t)(by + y + i) * cols + bx + x];
    __syncthreads();
    #pragma unroll
    for (int i = 0; i < 32; i += 8)
        ob[(size_t)(bx + y + i) * rows + by + x] = t[x][y + i];
}

// ---------------------------------------------------------------------------
// Row softmax over 2048 fp32 scores; writes split bf16 P.
// ---------------------------------------------------------------------------
__global__ __launch_bounds__(256)
void softmax_kernel(const float* __restrict__ S, __nv_bfloat16* __restrict__ Ph,
                    __nv_bfloat16* __restrict__ Pl)
{
    const float4* row = (const float4*)(S + (size_t)blockIdx.x * SEQ);
    __nv_bfloat16* ph = Ph + (size_t)blockIdx.x * SEQ;
    __nv_bfloat16* pl = Pl + (size_t)blockIdx.x * SEQ;
    const int tid = threadIdx.x;
    __shared__ float red[256];

    float4 v0 = row[tid];
    float4 v1 = row[tid + 256];

    float m = fmaxf(fmaxf(fmaxf(v0.x, v0.y), fmaxf(v0.z, v0.w)),
                    fmaxf(fmaxf(v1.x, v1.y), fmaxf(v1.z, v1.w)));
    red[tid] = m;
    __syncthreads();
    #pragma unroll
    for (int s = 128; s > 0; s >>= 1) {
        if (tid < s) red[tid] = fmaxf(red[tid], red[tid + s]);
        __syncthreads();
    }
    m = red[0];
    __syncthreads();

    v0.x = __expf(v0.x - m); v0.y = __expf(v0.y - m);
    v0.z = __expf(v0.z - m); v0.w = __expf(v0.w - m);
    v1.x = __expf(v1.x - m); v1.y = __expf(v1.y - m);
    v1.z = __expf(v1.z - m); v1.w = __expf(v1.w - m);

    float sum = (v0.x + v0.y + v0.z + v0.w) + (v1.x + v1.y + v1.z + v1.w);
    red[tid] = sum;
    __syncthreads();
    #pragma unroll
    for (int s = 128; s > 0; s >>= 1) {
        if (tid < s) red[tid] += red[tid + s];
        __syncthreads();
    }
    float inv = 1.0f / red[0];

    v0.x *= inv; v0.y *= inv; v0.z *= inv; v0.w *= inv;
    v1.x *= inv; v1.y *= inv; v1.z *= inv; v1.w *= inv;

    __nv_bfloat16 hx, lx, hy, ly, hz, lz, hw, lw;
    uint2 uh, ul;
    split_bf16(v0.x, hx, lx); split_bf16(v0.y, hy, ly);
    split_bf16(v0.z, hz, lz); split_bf16(v0.w, hw, lw);
    uh.x = pack2(hx, hy); uh.y = pack2(hz, hw);
    ul.x = pack2(lx, ly); ul.y = pack2(lz, lw);
    *(uint2*)&ph[tid * 4] = uh;
    *(uint2*)&pl[tid * 4] = ul;
    split_bf16(v1.x, hx, lx); split_bf16(v1.y, hy, ly);
    split_bf16(v1.z, hz, lz); split_bf16(v1.w, hw, lw);
    uh.x = pack2(hx, hy); uh.y = pack2(hz, hw);
    ul.x = pack2(lx, ly); ul.y = pack2(lz, lw);
    *(uint2*)&ph[(tid + 256) * 4] = uh;
    *(uint2*)&pl[(tid + 256) * 4] = ul;
}

// ---------------------------------------------------------------------------
// Host-side plumbing
// ---------------------------------------------------------------------------
extern "C" void kernel_launch(void* const* d_in, const int* in_sizes, int n_in,
                              void* d_out, int out_size)
{
    const float* x_a   = (const float*)d_in[0];
    const float* x_b   = (const float*)d_in[1];
    const float* sa_wq = (const float*)d_in[2];
    const float* sa_bq = (const float*)d_in[3];
    const float* sa_wk = (const float*)d_in[4];
    const float* sa_bk = (const float*)d_in[5];
    const float* sa_wv = (const float*)d_in[6];
    const float* sa_bv = (const float*)d_in[7];
    const float* sa_wo = (const float*)d_in[8];
    const float* sa_bo = (const float*)d_in[9];
    const float* ca_wq = (const float*)d_in[10];
    const float* ca_bq = (const float*)d_in[11];
    const float* ca_wk = (const float*)d_in[12];
    const float* ca_bk = (const float*)d_in[13];
    const float* ca_wv = (const float*)d_in[14];
    const float* ca_bv = (const float*)d_in[15];
    const float* ca_wo = (const float*)d_in[16];
    const float* ca_bo = (const float*)d_in[17];
    float* out = (float*)d_out;

    cudaFuncSetAttribute(mma_gemm<true,  false, false, true>,
                         cudaFuncAttributeMaxDynamicSharedMemorySize, SMEM_DYN);
    cudaFuncSetAttribute(mma_gemm<false, false, true,  false>,
                         cudaFuncAttributeMaxDynamicSharedMemorySize, SMEM_DYN);
    cudaFuncSetAttribute(mma_gemm<false, false, false, true>,
                         cudaFuncAttributeMaxDynamicSharedMemorySize, SMEM_DYN);
    cudaFuncSetAttribute(mma_gemm<true,  true,  true,  true>,
                         cudaFuncAttributeMaxDynamicSharedMemorySize, SMEM_DYN);
    cudaFuncSetAttribute(mma_gemm<true,  true,  true,  false>,
                         cudaFuncAttributeMaxDynamicSharedMemorySize, SMEM_DYN);

    float *s, *xb2;
    __nv_bfloat16 *xbh, *xbl, *xah, *xal, *qh, *ql, *kh, *kl, *vh, *vl;
    __nv_bfloat16 *vth, *vtl, *ph, *pl, *x2h, *x2l, *ath, *atl, *wth, *wtl;
    cudaGetSymbolAddress((void**)&s,   g_s);
    cudaGetSymbolAddress((void**)&xb2, g_xb2);
    cudaGetSymbolAddress((void**)&xbh, g_xbh); cudaGetSymbolAddress((void**)&xbl, g_xbl);
    cudaGetSymbolAddress((void**)&xah, g_xah); cudaGetSymbolAddress((void**)&xal, g_xal);
    cudaGetSymbolAddress((void**)&qh,  g_qh);  cudaGetSymbolAddress((void**)&ql,  g_ql);
    cudaGetSymbolAddress((void**)&kh,  g_kh);  cudaGetSymbolAddress((void**)&kl,  g_kl);
    cudaGetSymbolAddress((void**)&vh,  g_vh);  cudaGetSymbolAddress((void**)&vl,  g_vl);
    cudaGetSymbolAddress((void**)&vth, g_vth); cudaGetSymbolAddress((void**)&vtl, g_vtl);
    cudaGetSymbolAddress((void**)&ph,  g_ph);  cudaGetSymbolAddress((void**)&pl,  g_pl);
    cudaGetSymbolAddress((void**)&x2h, g_x2h); cudaGetSymbolAddress((void**)&x2l, g_x2l);
    cudaGetSymbolAddress((void**)&ath, g_ath); cudaGetSymbolAddress((void**)&atl, g_atl);
    cudaGetSymbolAddress((void**)&wth, g_wth); cudaGetSymbolAddress((void**)&wtl, g_wtl);

    const int M = BATCH * SEQ;                  // 16384
    const size_t qkvS = (size_t)SEQ * DB;
    const size_t sS   = (size_t)SEQ * SEQ;
    const int WSZ = DB * DB;

    // ---- prep: 3 launches so ncu (-s 5) lands on a GEMM -------------------
    {
        WPack p;
        const float* srcs[8] = {sa_wq, sa_wk, sa_wv, sa_wo, ca_wq, ca_wk, ca_wv, ca_wo};
        for (int i = 0; i < 8; i++) {
            p.src[i] = srcs[i];
            p.h[i] = wth + i * WSZ;
            p.l[i] = wtl + i * WSZ;
            p.rows[i] = (i == 4) ? DA : DB;
        }
        dim3 b(32, 8), g(DB / 32, DB / 32, 8);
        transpose_split_all<<<g, b>>>(p);
        size_t nb4 = (size_t)M * DB / 4, na4 = (size_t)M * DA / 4;
        split_kernel<<<(unsigned)((nb4 + 255) / 256), 256>>>(x_b, xbh, xbl, nb4);
        split_kernel<<<(unsigned)((na4 + 255) / 256), 256>>>(x_a, xah, xal, na4);
    }

    // ================= Self-attention on x_b ===============================
    {   // launches 3,4,5 (ncu profiles #5 = V projection GEMM)
        dim3 g(DB / 128, M / 128, 1);
        mma_gemm<true, false, false, true><<<g, 256, SMEM_DYN>>>(
            xbh, xbl, wth + 0 * WSZ, wtl + 0 * WSZ, sa_bq, nullptr,
            nullptr, qh, ql, M, DB, DB, 1.0f, 0, 0, 0);
        mma_gemm<true, false, false, true><<<g, 256, SMEM_DYN>>>(
            xbh, xbl, wth + 1 * WSZ, wtl + 1 * WSZ, sa_bk, nullptr,
            nullptr, kh, kl, M, DB, DB, 1.0f, 0, 0, 0);
        mma_gemm<true, false, false, true><<<g, 256, SMEM_DYN>>>(
            xbh, xbl, wth + 2 * WSZ, wtl + 2 * WSZ, sa_bv, nullptr,
            nullptr, vh, vl, M, DB, DB, 1.0f, 0, 0, 0);
    }
    {   // scores = Q @ K^T / 32 -> fp32
        dim3 g(SEQ / 128, SEQ / 128, BATCH);
        mma_gemm<false, false, true, false><<<g, 256, SMEM_DYN>>>(
            qh, ql, kh, kl, nullptr, nullptr, s, nullptr, nullptr,
            SEQ, SEQ, DB, 1.0f / 32.0f, qkvS, qkvS, sS);
    }
    softmax_kernel<<<BATCH * SEQ, 256>>>(s, ph, pl);
    {   // V^T per batch (bf16 x2)
        dim3 b(32, 8), g(DB / 32, SEQ / 32, BATCH);
        transpose16<<<g, b>>>((const uint16_t*)vh, (uint16_t*)vth, SEQ, DB);
        transpose16<<<g, b>>>((const uint16_t*)vl, (uint16_t*)vtl, SEQ, DB);
    }
    {   // attn = P @ V -> split
        dim3 g(DB / 128, SEQ / 128, BATCH);
        mma_gemm<false, false, false, true><<<g, 256, SMEM_DYN>>>(
            ph, pl, vth, vtl, nullptr, nullptr, nullptr, ath, atl,
            SEQ, DB, SEQ, 1.0f, sS, qkvS, qkvS);
    }
    {   // xb2 = x_b + attn @ Wo + bo  -> fp32 + split
        dim3 g(DB / 128, M / 128, 1);
        mma_gemm<true, true, true, true><<<g, 256, SMEM_DYN>>>(
            ath, atl, wth + 3 * WSZ, wtl + 3 * WSZ, sa_bo, x_b,
            xb2, x2h, x2l, M, DB, DB, 1.0f, 0, 0, 0);
    }

    // ================= Cross-attention =====================================
    {
        dim3 g(DB / 128, M / 128, 1);
        mma_gemm<true, false, false, true><<<g, 256, SMEM_DYN>>>(
            xah, xal, wth + 4 * WSZ, wtl + 4 * WSZ, ca_bq, nullptr,
            nullptr, qh, ql, M, DB, DA, 1.0f, 0, 0, 0);
        mma_gemm<true, false, false, true><<<g, 256, SMEM_DYN>>>(
            x2h, x2l, wth + 5 * WSZ, wtl + 5 * WSZ, ca_bk, nullptr,
            nullptr, kh, kl, M, DB, DB, 1.0f, 0, 0, 0);
        mma_gemm<true, false, false, true><<<g, 256, SMEM_DYN>>>(
            x2h, x2l, wth + 6 * WSZ, wtl + 6 * WSZ, ca_bv, nullptr,
            nullptr, vh, vl, M, DB, DB, 1.0f, 0, 0, 0);
    }
    {   // scores = Q @ K^T / sqrt(768)
        dim3 g(SEQ / 128, SEQ / 128, BATCH);
        mma_gemm<false, false, true, false><<<g, 256, SMEM_DYN>>>(
            qh, ql, kh, kl, nullptr, nullptr, s, nullptr, nullptr,
            SEQ, SEQ, DB, 1.0f / sqrtf((float)DA), qkvS, qkvS, sS);
    }
    softmax_kernel<<<BATCH * SEQ, 256>>>(s, ph, pl);
    {
        dim3 b(32, 8), g(DB / 32, SEQ / 32, BATCH);
        transpose16<<<g, b>>>((const uint16_t*)vh, (uint16_t*)vth, SEQ, DB);
        transpose16<<<g, b>>>((const uint16_t*)vl, (uint16_t*)vtl, SEQ, DB);
    }
    {
        dim3 g(DB / 128, SEQ / 128, BATCH);
        mma_gemm<false, false, false, true><<<g, 256, SMEM_DYN>>>(
            ph, pl, vth, vtl, nullptr, nullptr, nullptr, ath, atl,
            SEQ, DB, SEQ, 1.0f, sS, qkvS, qkvS);
    }
    {   // out = xb2 + attn @ Wo + bo -> fp32 only
        dim3 g(DB / 128, M / 128, 1);
        mma_gemm<true, true, true, false><<<g, 256, SMEM_DYN>>>(
            ath, atl, wth + 7 * WSZ, wtl + 7 * WSZ, ca_bo, xb2,
            out, nullptr, nullptr, M, DB, DB, 1.0f, 0, 0, 0);
    }
}

// round 12
// speedup vs baseline: 1.2784x; 1.2784x over previous
#include <cuda_runtime.h>
#include <cuda_fp16.h>
#include <cstdint>
#include <math.h>

#define BATCH 8
#define SEQ   2048
#define DA    768
#define DB    1024

// ---------------- scratch (device globals; module-load allocation) ---------
__device__ float g_s   [BATCH * SEQ * SEQ];            // fp32 scores
__device__ float g_xb2 [BATCH * SEQ * DB];             // fp32 residual
// fp16 hi/lo pairs
__device__ __half g_xbh[BATCH * SEQ * DB],  g_xbl[BATCH * SEQ * DB];
__device__ __half g_xah[BATCH * SEQ * DA],  g_xal[BATCH * SEQ * DA];
__device__ __half g_qh [BATCH * SEQ * DB],  g_ql [BATCH * SEQ * DB];
__device__ __half g_kh [BATCH * SEQ * DB],  g_kl [BATCH * SEQ * DB];
__device__ __half g_vh [BATCH * SEQ * DB],  g_vl [BATCH * SEQ * DB];
__device__ __half g_vth[BATCH * SEQ * DB],  g_vtl[BATCH * SEQ * DB];
__device__ __half g_ph [BATCH * SEQ * SEQ], g_pl [BATCH * SEQ * SEQ];
__device__ __half g_x2h[BATCH * SEQ * DB],  g_x2l[BATCH * SEQ * DB];
__device__ __half g_ath[BATCH * SEQ * DB],  g_atl[BATCH * SEQ * DB];
__device__ __half g_wth[8 * DB * DB],       g_wtl[8 * DB * DB];

// ---------------- helpers ---------------------------------------------------
__device__ __forceinline__ void split_h(float x, __half& h, __half& l) {
    h = __float2half_rn(x);
    l = __float2half_rn(x - __half2float(h));
}
__device__ __forceinline__ uint32_t pack2h(__half a, __half b) {
    __half2 t; t.x = a; t.y = b;
    return *(uint32_t*)&t;
}
__device__ __forceinline__ uint32_t smem_u32(const void* p) {
    uint32_t a;
    asm("{ .reg .u64 t; cvta.to.shared.u64 t, %1; cvt.u32.u64 %0, t; }"
        : "=r"(a) : "l"(p));
    return a;
}
__device__ __forceinline__ void cp16(uint32_t dst, const void* src) {
    asm volatile("cp.async.cg.shared.global [%0], [%1], 16;"
                 :: "r"(dst), "l"(src));
}
#define CP_COMMIT() asm volatile("cp.async.commit_group;")
#define CP_WAIT(n)  asm volatile("cp.async.wait_group %0;" :: "n"(n))

#define MMA_F16(acc, Af, Bf)                                                   \
    asm volatile(                                                              \
        "mma.sync.aligned.m16n8k16.row.col.f32.f16.f16.f32 "                   \
        "{%0,%1,%2,%3},{%4,%5,%6,%7},{%8,%9},{%0,%1,%2,%3};"                   \
        : "+f"((acc)[0]), "+f"((acc)[1]), "+f"((acc)[2]), "+f"((acc)[3])       \
        : "r"((Af)[0]), "r"((Af)[1]), "r"((Af)[2]), "r"((Af)[3]),              \
          "r"((Bf)[0]), "r"((Bf)[1]))

#define LDSM4(r0, r1, r2, r3, a)                                               \
    asm volatile("ldmatrix.sync.aligned.m8n8.x4.shared.b16 {%0,%1,%2,%3}, [%4];" \
        : "=r"(r0), "=r"(r1), "=r"(r2), "=r"(r3) : "r"(a))

// ---------------------------------------------------------------------------
// fp16 split GEMM via mma.sync:
//   C = alpha * A @ B^T [+ bias] [+ res];  A:[M,K] (h[,l]), B:[N,K] (h,l).
//   PASSES==2: Ah*Bh + Ah*Bl      (error ~2^-11/sqrt(3), Al unused)
//   PASSES==3: + Al*Bh            (error ~u^2)
//   CTA tile 128x64, warp tile 32x32 (8 warps as 4Mx2N), KC=32,
//   cp.async double-buffer, ldmatrix fragments, 3 CTAs/SM target.
// ---------------------------------------------------------------------------
#define ROWB 80
#define OFF_BH 10240      /* A-h: rows 0..127 x 80B */
#define OFF_BL 15360
#define OFF_AL 20480      /* only present for PASSES==3 */

template<int PASSES, bool HAS_BIAS, bool HAS_RES, bool WRITE_F32, bool WRITE_SPLIT>
__global__ __launch_bounds__(256, 3)
void mma_gemm(const __half* __restrict__ Ah, const __half* __restrict__ Al,
              const __half* __restrict__ Bh, const __half* __restrict__ Bl,
              const float* __restrict__ bias, const float* __restrict__ res,
              float* __restrict__ C, __half* __restrict__ Ch,
              __half* __restrict__ Cl,
              int M, int N, int K, float alpha,
              size_t sA, size_t sB, size_t sC)
{
    constexpr int STAGE = (PASSES == 3) ? 30720 : 20480;
    extern __shared__ char smem[];
    const uint32_t sb = smem_u32(smem);

    const int bz = blockIdx.z;
    Ah += (size_t)bz * sA;
    if (PASSES == 3) Al += (size_t)bz * sA;
    Bh += (size_t)bz * sB; Bl += (size_t)bz * sB;
    const size_t cOff = (size_t)bz * sC;

    const int row0 = blockIdx.y * 128;
    const int col0 = blockIdx.x * 64;
    const int tid  = threadIdx.x;
    const int wid  = tid >> 5;
    const int lane = tid & 31;
    const int wm   = wid >> 1;          // 0..3  (M, 32 rows each)
    const int wn   = wid & 1;           // 0..1  (N, 32 cols each)
    const int lr   = lane >> 2;         // 0..7
    const int lc   = lane & 3;          // 0..3

    const int f0r = tid >> 2;           // 0..63
    const int f0c = tid & 3;            // 16B slot in 64B row payload
    const int g   = lane >> 3, ri = lane & 7;
    const int aR  = (g & 1) * 8 + ri;   // A ldmatrix row-in-16
    const int aC  = (g >> 1) * 16;
    const int bR  = (g >> 1) * 8 + ri;  // B ldmatrix row-in-16
    const int bC  = (g & 1) * 16;

    float acc[2][4][4];
    #pragma unroll
    for (int a = 0; a < 2; a++)
        #pragma unroll
        for (int b = 0; b < 4; b++)
            #pragma unroll
            for (int c = 0; c < 4; c++)
                acc[a][b][c] = 0.0f;

    const int nCh = K / 32;

    auto load_stage = [&](int st, int ch) {
        const uint32_t base = sb + st * STAGE;
        const uint32_t d = f0r * ROWB + f0c * 16;
        // A-h rows 0..127
        #pragma unroll
        for (int i = 0; i < 2; i++) {
            size_t oa = (size_t)(row0 + f0r + i * 64) * K + ch * 32 + f0c * 8;
            cp16(base + d + i * (64 * ROWB), Ah + oa);
            if (PASSES == 3)
                cp16(base + OFF_AL + d + i * (64 * ROWB), Al + oa);
        }
        // B rows 0..63 (h and l)
        size_t ob = (size_t)(col0 + f0r) * K + ch * 32 + f0c * 8;
        cp16(base + OFF_BH + d, Bh + ob);
        cp16(base + OFF_BL + d, Bl + ob);
        CP_COMMIT();
    };

    load_stage(0, 0);

    for (int ch = 0; ch < nCh; ch++) {
        if (ch + 1 < nCh) { load_stage((ch + 1) & 1, ch + 1); CP_WAIT(1); }
        else              { CP_WAIT(0); }
        __syncthreads();

        const uint32_t base = sb + (ch & 1) * STAGE;
        #pragma unroll
        for (int s = 0; s < 2; s++) {
            uint32_t Afh[2][4], Afl[2][4], Bfh[4][2], Bfl[4][2];
            #pragma unroll
            for (int mt = 0; mt < 2; mt++) {
                uint32_t ar = base + (wm * 32 + mt * 16 + aR) * ROWB + s * 32 + aC;
                LDSM4(Afh[mt][0], Afh[mt][1], Afh[mt][2], Afh[mt][3], ar);
                if (PASSES == 3)
                    LDSM4(Afl[mt][0], Afl[mt][1], Afl[mt][2], Afl[mt][3], ar + OFF_AL);
            }
            #pragma unroll
            for (int np = 0; np < 2; np++) {
                uint32_t br = base + OFF_BH + (wn * 32 + np * 16 + bR) * ROWB + s * 32 + bC;
                LDSM4(Bfh[2*np][0], Bfh[2*np][1], Bfh[2*np+1][0], Bfh[2*np+1][1], br);
                LDSM4(Bfl[2*np][0], Bfl[2*np][1], Bfl[2*np+1][0], Bfl[2*np+1][1],
                      br + (OFF_BL - OFF_BH));
            }
            #pragma unroll
            for (int mt = 0; mt < 2; mt++)
                #pragma unroll
                for (int nt = 0; nt < 4; nt++) {
                    MMA_F16(acc[mt][nt], Afh[mt], Bfh[nt]);
                    MMA_F16(acc[mt][nt], Afh[mt], Bfl[nt]);
                    if (PASSES == 3)
                        MMA_F16(acc[mt][nt], Afl[mt], Bfh[nt]);
                }
        }
        __syncthreads();
    }

    // ---- epilogue ----
    const float* __restrict__ R = HAS_RES ? (res + cOff) : nullptr;
    #pragma unroll
    for (int mt = 0; mt < 2; mt++) {
        #pragma unroll
        for (int nt = 0; nt < 4; nt++) {
            int r = row0 + wm * 32 + mt * 16 + lr;
            int c = col0 + wn * 32 + nt * 8 + lc * 2;
            float2 o0, o1;
            o0.x = acc[mt][nt][0] * alpha; o0.y = acc[mt][nt][1] * alpha;
            o1.x = acc[mt][nt][2] * alpha; o1.y = acc[mt][nt][3] * alpha;
            if (HAS_BIAS) {
                float2 bv = *(const float2*)&bias[c];
                o0.x += bv.x; o0.y += bv.y;
                o1.x += bv.x; o1.y += bv.y;
            }
            if (HAS_RES) {
                float2 r0 = *(const float2*)&R[(size_t)r * N + c];
                float2 r1 = *(const float2*)&R[(size_t)(r + 8) * N + c];
                o0.x += r0.x; o0.y += r0.y;
                o1.x += r1.x; o1.y += r1.y;
            }
            if (WRITE_F32) {
                *(float2*)&C[cOff + (size_t)r * N + c]       = o0;
                *(float2*)&C[cOff + (size_t)(r + 8) * N + c] = o1;
            }
            if (WRITE_SPLIT) {
                __half hx, lx, hy, ly;
                split_h(o0.x, hx, lx); split_h(o0.y, hy, ly);
                *(uint32_t*)&Ch[cOff + (size_t)r * N + c] = pack2h(hx, hy);
                *(uint32_t*)&Cl[cOff + (size_t)r * N + c] = pack2h(lx, ly);
                split_h(o1.x, hx, lx); split_h(o1.y, hy, ly);
                *(uint32_t*)&Ch[cOff + (size_t)(r + 8) * N + c] = pack2h(hx, hy);
                *(uint32_t*)&Cl[cOff + (size_t)(r + 8) * N + c] = pack2h(lx, ly);
            }
        }
    }
}

#define SMEM2 (2 * 20480)
#define SMEM3 (2 * 30720)

// ---------------------------------------------------------------------------
// Elementwise split: fp32 -> (hi, lo) fp16.
// ---------------------------------------------------------------------------
__global__ __launch_bounds__(256)
void split_kernel(const float* __restrict__ in, __half* __restrict__ h,
                  __half* __restrict__ l, size_t n4)
{
    size_t i = (size_t)blockIdx.x * 256 + threadIdx.x;
    if (i >= n4) return;
    float4 v = ((const float4*)in)[i];
    __half hx, lx, hy, ly, hz, lz, hw, lw;
    split_h(v.x, hx, lx); split_h(v.y, hy, ly);
    split_h(v.z, hz, lz); split_h(v.w, hw, lw);
    uint2 uh, ul;
    uh.x = pack2h(hx, hy); uh.y = pack2h(hz, hw);
    ul.x = pack2h(lx, ly); ul.y = pack2h(lz, lw);
    *(uint2*)&h[i * 4] = uh;
    *(uint2*)&l[i * 4] = ul;
}

// ---------------------------------------------------------------------------
// All-weights transpose+split in ONE launch (z = weight slot 0..7).
// ---------------------------------------------------------------------------
struct WPack {
    const float* src[8];
    __half* h[8];
    __half* l[8];
    int rows[8];
};

__global__ void transpose_split_all(WPack p)
{
    __shared__ float t[32][33];
    const int z = blockIdx.z;
    const int rows = p.rows[z];
    const int by = blockIdx.y * 32;
    if (by >= rows) return;
    const float* in = p.src[z];
    __half* h = p.h[z];
    __half* l = p.l[z];
    int bx = blockIdx.x * 32;
    int x = threadIdx.x, y = threadIdx.y;
    #pragma unroll
    for (int i = 0; i < 32; i += 8)
        t[y + i][x] = in[(size_t)(by + y + i) * DB + bx + x];
    __syncthreads();
    #pragma unroll
    for (int i = 0; i < 32; i += 8) {
        float v = t[x][y + i];
        __half hv, lv;
        split_h(v, hv, lv);
        size_t o = (size_t)(bx + y + i) * rows + by + x;
        h[o] = hv; l[o] = lv;
    }
}

// ---------------------------------------------------------------------------
// 16-bit transpose, batched over z.
// ---------------------------------------------------------------------------
__global__ void transpose16(const uint16_t* __restrict__ in,
                            uint16_t* __restrict__ outp, int rows, int cols)
{
    __shared__ uint16_t t[32][34];
    const size_t boff = (size_t)blockIdx.z * rows * cols;
    const uint16_t* ib = in + boff;
    uint16_t* ob = outp + boff;
    int bx = blockIdx.x * 32, by = blockIdx.y * 32;
    int x = threadIdx.x, y = threadIdx.y;
    #pragma unroll
    for (int i = 0; i < 32; i += 8)
        t[y + i][x] = ib[(size_t)(by + y + i) * cols + bx + x];
    __syncthreads();
    #pragma unroll
    for (int i = 0; i < 32; i += 8)
        ob[(size_t)(bx + y + i) * rows + by + x] = t[x][y + i];
}

// ---------------------------------------------------------------------------
// Row softmax over 2048 fp32 scores; writes split fp16 P.
// ---------------------------------------------------------------------------
__global__ __launch_bounds__(256)
void softmax_kernel(const float* __restrict__ S, __half* __restrict__ Ph,
                    __half* __restrict__ Pl)
{
    const float4* row = (const float4*)(S + (size_t)blockIdx.x * SEQ);
    __half* ph = Ph + (size_t)blockIdx.x * SEQ;
    __half* pl = Pl + (size_t)blockIdx.x * SEQ;
    const int tid = threadIdx.x;
    __shared__ float red[256];

    float4 v0 = row[tid];
    float4 v1 = row[tid + 256];

    float m = fmaxf(fmaxf(fmaxf(v0.x, v0.y), fmaxf(v0.z, v0.w)),
                    fmaxf(fmaxf(v1.x, v1.y), fmaxf(v1.z, v1.w)));
    red[tid] = m;
    __syncthreads();
    #pragma unroll
    for (int s = 128; s > 0; s >>= 1) {
        if (tid < s) red[tid] = fmaxf(red[tid], red[tid + s]);
        __syncthreads();
    }
    m = red[0];
    __syncthreads();

    v0.x = __expf(v0.x - m); v0.y = __expf(v0.y - m);
    v0.z = __expf(v0.z - m); v0.w = __expf(v0.w - m);
    v1.x = __expf(v1.x - m); v1.y = __expf(v1.y - m);
    v1.z = __expf(v1.z - m); v1.w = __expf(v1.w - m);

    float sum = (v0.x + v0.y + v0.z + v0.w) + (v1.x + v1.y + v1.z + v1.w);
    red[tid] = sum;
    __syncthreads();
    #pragma unroll
    for (int s = 128; s > 0; s >>= 1) {
        if (tid < s) red[tid] += red[tid + s];
        __syncthreads();
    }
    float inv = 1.0f / red[0];

    v0.x *= inv; v0.y *= inv; v0.z *= inv; v0.w *= inv;
    v1.x *= inv; v1.y *= inv; v1.z *= inv; v1.w *= inv;

    __half hx, lx, hy, ly, hz, lz, hw, lw;
    uint2 uh, ul;
    split_h(v0.x, hx, lx); split_h(v0.y, hy, ly);
    split_h(v0.z, hz, lz); split_h(v0.w, hw, lw);
    uh.x = pack2h(hx, hy); uh.y = pack2h(hz, hw);
    ul.x = pack2h(lx, ly); ul.y = pack2h(lz, lw);
    *(uint2*)&ph[tid * 4] = uh;
    *(uint2*)&pl[tid * 4] = ul;
    split_h(v1.x, hx, lx); split_h(v1.y, hy, ly);
    split_h(v1.z, hz, lz); split_h(v1.w, hw, lw);
    uh.x = pack2h(hx, hy); uh.y = pack2h(hz, hw);
    ul.x = pack2h(lx, ly); ul.y = pack2h(lz, lw);
    *(uint2*)&ph[(tid + 256) * 4] = uh;
    *(uint2*)&pl[(tid + 256) * 4] = ul;
}

// ---------------------------------------------------------------------------
// Host-side plumbing
// ---------------------------------------------------------------------------
extern "C" void kernel_launch(void* const* d_in, const int* in_sizes, int n_in,
                              void* d_out, int out_size)
{
    const float* x_a   = (const float*)d_in[0];
    const float* x_b   = (const float*)d_in[1];
    const float* sa_wq = (const float*)d_in[2];
    const float* sa_bq = (const float*)d_in[3];
    const float* sa_wk = (const float*)d_in[4];
    const float* sa_bk = (const float*)d_in[5];
    const float* sa_wv = (const float*)d_in[6];
    const float* sa_bv = (const float*)d_in[7];
    const float* sa_wo = (const float*)d_in[8];
    const float* sa_bo = (const float*)d_in[9];
    const float* ca_wq = (const float*)d_in[10];
    const float* ca_bq = (const float*)d_in[11];
    const float* ca_wk = (const float*)d_in[12];
    const float* ca_bk = (const float*)d_in[13];
    const float* ca_wv = (const float*)d_in[14];
    const float* ca_bv = (const float*)d_in[15];
    const float* ca_wo = (const float*)d_in[16];
    const float* ca_bo = (const float*)d_in[17];
    float* out = (float*)d_out;

    cudaFuncSetAttribute(mma_gemm<2, true,  false, false, true>,
                         cudaFuncAttributeMaxDynamicSharedMemorySize, SMEM2);
    cudaFuncSetAttribute(mma_gemm<3, false, false, true,  false>,
                         cudaFuncAttributeMaxDynamicSharedMemorySize, SMEM3);
    cudaFuncSetAttribute(mma_gemm<2, false, false, false, true>,
                         cudaFuncAttributeMaxDynamicSharedMemorySize, SMEM2);
    cudaFuncSetAttribute(mma_gemm<2, true,  true,  true,  true>,
                         cudaFuncAttributeMaxDynamicSharedMemorySize, SMEM2);
    cudaFuncSetAttribute(mma_gemm<2, true,  true,  true,  false>,
                         cudaFuncAttributeMaxDynamicSharedMemorySize, SMEM2);

    float *s, *xb2;
    __half *xbh, *xbl, *xah, *xal, *qh, *ql, *kh, *kl, *vh, *vl;
    __half *vth, *vtl, *ph, *pl, *x2h, *x2l, *ath, *atl, *wth, *wtl;
    cudaGetSymbolAddress((void**)&s,   g_s);
    cudaGetSymbolAddress((void**)&xb2, g_xb2);
    cudaGetSymbolAddress((void**)&xbh, g_xbh); cudaGetSymbolAddress((void**)&xbl, g_xbl);
    cudaGetSymbolAddress((void**)&xah, g_xah); cudaGetSymbolAddress((void**)&xal, g_xal);
    cudaGetSymbolAddress((void**)&qh,  g_qh);  cudaGetSymbolAddress((void**)&ql,  g_ql);
    cudaGetSymbolAddress((void**)&kh,  g_kh);  cudaGetSymbolAddress((void**)&kl,  g_kl);
    cudaGetSymbolAddress((void**)&vh,  g_vh);  cudaGetSymbolAddress((void**)&vl,  g_vl);
    cudaGetSymbolAddress((void**)&vth, g_vth); cudaGetSymbolAddress((void**)&vtl, g_vtl);
    cudaGetSymbolAddress((void**)&ph,  g_ph);  cudaGetSymbolAddress((void**)&pl,  g_pl);
    cudaGetSymbolAddress((void**)&x2h, g_x2h); cudaGetSymbolAddress((void**)&x2l, g_x2l);
    cudaGetSymbolAddress((void**)&ath, g_ath); cudaGetSymbolAddress((void**)&atl, g_atl);
    cudaGetSymbolAddress((void**)&wth, g_wth); cudaGetSymbolAddress((void**)&wtl, g_wtl);

    const int M = BATCH * SEQ;                  // 16384
    const size_t qkvS = (size_t)SEQ * DB;
    const size_t sS   = (size_t)SEQ * SEQ;
    const int WSZ = DB * DB;

    // ---- prep (3 launches) -------------------------------------------------
    {
        WPack p;
        const float* srcs[8] = {sa_wq, sa_wk, sa_wv, sa_wo, ca_wq, ca_wk, ca_wv, ca_wo};
        for (int i = 0; i < 8; i++) {
            p.src[i] = srcs[i];
            p.h[i] = wth + i * WSZ;
            p.l[i] = wtl + i * WSZ;
            p.rows[i] = (i == 4) ? DA : DB;
        }
        dim3 b(32, 8), g(DB / 32, DB / 32, 8);
        transpose_split_all<<<g, b>>>(p);
        size_t nb4 = (size_t)M * DB / 4, na4 = (size_t)M * DA / 4;
        split_kernel<<<(unsigned)((nb4 + 255) / 256), 256>>>(x_b, xbh, xbl, nb4);
        split_kernel<<<(unsigned)((na4 + 255) / 256), 256>>>(x_a, xah, xal, na4);
    }

    // ================= Self-attention on x_b ===============================
    {   // q,k,v projections (2-pass; launch #5 = V proj for ncu)
        dim3 g(DB / 64, M / 128, 1);
        mma_gemm<2, true, false, false, true><<<g, 256, SMEM2>>>(
            xbh, nullptr, wth + 0 * WSZ, wtl + 0 * WSZ, sa_bq, nullptr,
            nullptr, qh, ql, M, DB, DB, 1.0f, 0, 0, 0);
        mma_gemm<2, true, false, false, true><<<g, 256, SMEM2>>>(
            xbh, nullptr, wth + 1 * WSZ, wtl + 1 * WSZ, sa_bk, nullptr,
            nullptr, kh, kl, M, DB, DB, 1.0f, 0, 0, 0);
        mma_gemm<2, true, false, false, true><<<g, 256, SMEM2>>>(
            xbh, nullptr, wth + 2 * WSZ, wtl + 2 * WSZ, sa_bv, nullptr,
            nullptr, vh, vl, M, DB, DB, 1.0f, 0, 0, 0);
    }
    {   // scores = Q @ K^T / 32  (3-pass for safety at the softmax)
        dim3 g(SEQ / 64, SEQ / 128, BATCH);
        mma_gemm<3, false, false, true, false><<<g, 256, SMEM3>>>(
            qh, ql, kh, kl, nullptr, nullptr, s, nullptr, nullptr,
            SEQ, SEQ, DB, 1.0f / 32.0f, qkvS, qkvS, sS);
    }
    softmax_kernel<<<BATCH * SEQ, 256>>>(s, ph, pl);
    {   // V^T per batch
        dim3 b(32, 8), g(DB / 32, SEQ / 32, BATCH);
        transpose16<<<g, b>>>((const uint16_t*)vh, (uint16_t*)vth, SEQ, DB);
        transpose16<<<g, b>>>((const uint16_t*)vl, (uint16_t*)vtl, SEQ, DB);
    }
    {   // attn = P @ V (2-pass)
        dim3 g(DB / 64, SEQ / 128, BATCH);
        mma_gemm<2, false, false, false, true><<<g, 256, SMEM2>>>(
            ph, nullptr, vth, vtl, nullptr, nullptr, nullptr, ath, atl,
            SEQ, DB, SEQ, 1.0f, sS, qkvS, qkvS);
    }
    {   // xb2 = x_b + attn @ Wo + bo (2-pass)
        dim3 g(DB / 64, M / 128, 1);
        mma_gemm<2, true, true, true, true><<<g, 256, SMEM2>>>(
            ath, nullptr, wth + 3 * WSZ, wtl + 3 * WSZ, sa_bo, x_b,
            xb2, x2h, x2l, M, DB, DB, 1.0f, 0, 0, 0);
    }

    // ================= Cross-attention =====================================
    {
        dim3 g(DB / 64, M / 128, 1);
        mma_gemm<2, true, false, false, true><<<g, 256, SMEM2>>>(
            xah, nullptr, wth + 4 * WSZ, wtl + 4 * WSZ, ca_bq, nullptr,
            nullptr, qh, ql, M, DB, DA, 1.0f, 0, 0, 0);
        mma_gemm<2, true, false, false, true><<<g, 256, SMEM2>>>(
            x2h, nullptr, wth + 5 * WSZ, wtl + 5 * WSZ, ca_bk, nullptr,
            nullptr, kh, kl, M, DB, DB, 1.0f, 0, 0, 0);
        mma_gemm<2, true, false, false, true><<<g, 256, SMEM2>>>(
            x2h, nullptr, wth + 6 * WSZ, wtl + 6 * WSZ, ca_bv, nullptr,
            nullptr, vh, vl, M, DB, DB, 1.0f, 0, 0, 0);
    }
    {   // scores = Q @ K^T / sqrt(768) (3-pass)
        dim3 g(SEQ / 64, SEQ / 128, BATCH);
        mma_gemm<3, false, false, true, false><<<g, 256, SMEM3>>>(
            qh, ql, kh, kl, nullptr, nullptr, s, nullptr, nullptr,
            SEQ, SEQ, DB, 1.0f / sqrtf((float)DA), qkvS, qkvS, sS);
    }
    softmax_kernel<<<BATCH * SEQ, 256>>>(s, ph, pl);
    {
        dim3 b(32, 8), g(DB / 32, SEQ / 32, BATCH);
        transpose16<<<g, b>>>((const uint16_t*)vh, (uint16_t*)vth, SEQ, DB);
        transpose16<<<g, b>>>((const uint16_t*)vl, (uint16_t*)vtl, SEQ, DB);
    }
    {
        dim3 g(DB / 64, SEQ / 128, BATCH);
        mma_gemm<2, false, false, false, true><<<g, 256, SMEM2>>>(
            ph, nullptr, vth, vtl, nullptr, nullptr, nullptr, ath, atl,
            SEQ, DB, SEQ, 1.0f, sS, qkvS, qkvS);
    }
    {   // out = xb2 + attn @ Wo + bo (2-pass)
        dim3 g(DB / 64, M / 128, 1);
        mma_gemm<2, true, true, true, false><<<g, 256, SMEM2>>>(
            ath, nullptr, wth + 7 * WSZ, wtl + 7 * WSZ, ca_bo, xb2,
            out, nullptr, nullptr, M, DB, DB, 1.0f, 0, 0, 0);
    }
}

// round 13
// speedup vs baseline: 3.3021x; 2.5830x over previous
#include <cuda_runtime.h>
#include <cuda_fp16.h>
#include <cstdint>
#include <math.h>

#define BATCH 8
#define SEQ   2048
#define DA    768
#define DB    1024

// ---------------- scratch (device globals; module-load allocation) ---------
__device__ float g_s   [BATCH * SEQ * SEQ];            // fp32 scores
__device__ float g_xb2 [BATCH * SEQ * DB];             // fp32 residual
// fp16 operands (single precision level — 1-pass path)
__device__ __half g_xbh[BATCH * SEQ * DB];
__device__ __half g_xah[BATCH * SEQ * DA];
__device__ __half g_qh [BATCH * SEQ * DB];
__device__ __half g_kh [BATCH * SEQ * DB];
__device__ __half g_vh [BATCH * SEQ * DB];
__device__ __half g_vth[BATCH * SEQ * DB];
__device__ __half g_ph [BATCH * SEQ * SEQ];
__device__ __half g_x2h[BATCH * SEQ * DB];
__device__ __half g_ath[BATCH * SEQ * DB];
__device__ __half g_wth[8 * DB * DB];

// ---------------- helpers ---------------------------------------------------
__device__ __forceinline__ uint32_t pack2h(__half a, __half b) {
    __half2 t; t.x = a; t.y = b;
    return *(uint32_t*)&t;
}
__device__ __forceinline__ uint32_t smem_u32(const void* p) {
    uint32_t a;
    asm("{ .reg .u64 t; cvta.to.shared.u64 t, %1; cvt.u32.u64 %0, t; }"
        : "=r"(a) : "l"(p));
    return a;
}
__device__ __forceinline__ void cp16(uint32_t dst, const void* src) {
    asm volatile("cp.async.cg.shared.global [%0], [%1], 16;"
                 :: "r"(dst), "l"(src));
}
#define CP_COMMIT() asm volatile("cp.async.commit_group;")
#define CP_WAIT(n)  asm volatile("cp.async.wait_group %0;" :: "n"(n))

#define MMA_F16(acc, Af, Bf)                                                   \
    asm volatile(                                                              \
        "mma.sync.aligned.m16n8k16.row.col.f32.f16.f16.f32 "                   \
        "{%0,%1,%2,%3},{%4,%5,%6,%7},{%8,%9},{%0,%1,%2,%3};"                   \
        : "+f"((acc)[0]), "+f"((acc)[1]), "+f"((acc)[2]), "+f"((acc)[3])       \
        : "r"((Af)[0]), "r"((Af)[1]), "r"((Af)[2]), "r"((Af)[3]),              \
          "r"((Bf)[0]), "r"((Bf)[1]))

#define LDSM4(r0, r1, r2, r3, a)                                               \
    asm volatile("ldmatrix.sync.aligned.m8n8.x4.shared.b16 {%0,%1,%2,%3}, [%4];" \
        : "=r"(r0), "=r"(r1), "=r"(r2), "=r"(r3) : "r"(a))

// ---------------------------------------------------------------------------
// 1-pass fp16 GEMM via mma.sync (fp32 accum):
//   C = alpha * A @ B^T [+ bias] [+ res];  A:[M,K] fp16, B:[N,K] fp16.
//   CTA tile 128x64, warp tile 32x32 (8 warps as 4Mx2N), KC=32,
//   cp.async double-buffer, ldmatrix fragments.
// SMEM stage: A 128 rows x 80B (64B payload) + B 64 rows x 80B = 15360B.
// ---------------------------------------------------------------------------
#define ROWB 80
#define OFF_B 10240
#define STAGE 15360
#define SMEM_DYN (2 * STAGE)

template<bool HAS_BIAS, bool HAS_RES, bool WRITE_F32, bool WRITE_H>
__global__ __launch_bounds__(256, 3)
void mma_gemm(const __half* __restrict__ Ah, const __half* __restrict__ Bh,
              const float* __restrict__ bias, const float* __restrict__ res,
              float* __restrict__ C, __half* __restrict__ Ch,
              int M, int N, int K, float alpha,
              size_t sA, size_t sB, size_t sC)
{
    extern __shared__ char smem[];
    const uint32_t sb = smem_u32(smem);

    const int bz = blockIdx.z;
    Ah += (size_t)bz * sA;
    Bh += (size_t)bz * sB;
    const size_t cOff = (size_t)bz * sC;

    const int row0 = blockIdx.y * 128;
    const int col0 = blockIdx.x * 64;
    const int tid  = threadIdx.x;
    const int wid  = tid >> 5;
    const int lane = tid & 31;
    const int wm   = wid >> 1;          // 0..3  (M, 32 rows each)
    const int wn   = wid & 1;           // 0..1  (N, 32 cols each)
    const int lr   = lane >> 2;         // 0..7
    const int lc   = lane & 3;          // 0..3

    const int f0r = tid >> 2;           // 0..63
    const int f0c = tid & 3;            // 16B slot in 64B row payload
    const int g   = lane >> 3, ri = lane & 7;
    const int aR  = (g & 1) * 8 + ri;
    const int aC  = (g >> 1) * 16;
    const int bR  = (g >> 1) * 8 + ri;
    const int bC  = (g & 1) * 16;

    float acc[2][4][4];
    #pragma unroll
    for (int a = 0; a < 2; a++)
        #pragma unroll
        for (int b = 0; b < 4; b++)
            #pragma unroll
            for (int c = 0; c < 4; c++)
                acc[a][b][c] = 0.0f;

    const int nCh = K / 32;

    auto load_stage = [&](int st, int ch) {
        const uint32_t base = sb + st * STAGE;
        const uint32_t d = f0r * ROWB + f0c * 16;
        #pragma unroll
        for (int i = 0; i < 2; i++) {
            size_t oa = (size_t)(row0 + f0r + i * 64) * K + ch * 32 + f0c * 8;
            cp16(base + d + i * (64 * ROWB), Ah + oa);
        }
        size_t ob = (size_t)(col0 + f0r) * K + ch * 32 + f0c * 8;
        cp16(base + OFF_B + d, Bh + ob);
        CP_COMMIT();
    };

    load_stage(0, 0);

    for (int ch = 0; ch < nCh; ch++) {
        if (ch + 1 < nCh) { load_stage((ch + 1) & 1, ch + 1); CP_WAIT(1); }
        else              { CP_WAIT(0); }
        __syncthreads();

        const uint32_t base = sb + (ch & 1) * STAGE;
        #pragma unroll
        for (int s = 0; s < 2; s++) {
            uint32_t Af[2][4], Bf[4][2];
            #pragma unroll
            for (int mt = 0; mt < 2; mt++) {
                uint32_t ar = base + (wm * 32 + mt * 16 + aR) * ROWB + s * 32 + aC;
                LDSM4(Af[mt][0], Af[mt][1], Af[mt][2], Af[mt][3], ar);
            }
            #pragma unroll
            for (int np = 0; np < 2; np++) {
                uint32_t br = base + OFF_B + (wn * 32 + np * 16 + bR) * ROWB + s * 32 + bC;
                LDSM4(Bf[2*np][0], Bf[2*np][1], Bf[2*np+1][0], Bf[2*np+1][1], br);
            }
            #pragma unroll
            for (int mt = 0; mt < 2; mt++)
                #pragma unroll
                for (int nt = 0; nt < 4; nt++)
                    MMA_F16(acc[mt][nt], Af[mt], Bf[nt]);
        }
        __syncthreads();
    }

    // ---- epilogue ----
    const float* __restrict__ R = HAS_RES ? (res + cOff) : nullptr;
    #pragma unroll
    for (int mt = 0; mt < 2; mt++) {
        #pragma unroll
        for (int nt = 0; nt < 4; nt++) {
            int r = row0 + wm * 32 + mt * 16 + lr;
            int c = col0 + wn * 32 + nt * 8 + lc * 2;
            float2 o0, o1;
            o0.x = acc[mt][nt][0] * alpha; o0.y = acc[mt][nt][1] * alpha;
            o1.x = acc[mt][nt][2] * alpha; o1.y = acc[mt][nt][3] * alpha;
            if (HAS_BIAS) {
                float2 bv = *(const float2*)&bias[c];
                o0.x += bv.x; o0.y += bv.y;
                o1.x += bv.x; o1.y += bv.y;
            }
            if (HAS_RES) {
                float2 r0 = *(const float2*)&R[(size_t)r * N + c];
                float2 r1 = *(const float2*)&R[(size_t)(r + 8) * N + c];
                o0.x += r0.x; o0.y += r0.y;
                o1.x += r1.x; o1.y += r1.y;
            }
            if (WRITE_F32) {
                *(float2*)&C[cOff + (size_t)r * N + c]       = o0;
                *(float2*)&C[cOff + (size_t)(r + 8) * N + c] = o1;
            }
            if (WRITE_H) {
                *(uint32_t*)&Ch[cOff + (size_t)r * N + c] =
                    pack2h(__float2half_rn(o0.x), __float2half_rn(o0.y));
                *(uint32_t*)&Ch[cOff + (size_t)(r + 8) * N + c] =
                    pack2h(__float2half_rn(o1.x), __float2half_rn(o1.y));
            }
        }
    }
}

// ---------------------------------------------------------------------------
// Elementwise convert fp32 -> fp16.
// ---------------------------------------------------------------------------
__global__ __launch_bounds__(256)
void convert_kernel(const float* __restrict__ in, __half* __restrict__ h, size_t n4)
{
    size_t i = (size_t)blockIdx.x * 256 + threadIdx.x;
    if (i >= n4) return;
    float4 v = ((const float4*)in)[i];
    uint2 uh;
    uh.x = pack2h(__float2half_rn(v.x), __float2half_rn(v.y));
    uh.y = pack2h(__float2half_rn(v.z), __float2half_rn(v.w));
    *(uint2*)&h[i * 4] = uh;
}

// ---------------------------------------------------------------------------
// All-weights transpose+convert in ONE launch (z = weight slot 0..7).
// ---------------------------------------------------------------------------
struct WPack {
    const float* src[8];
    __half* h[8];
    int rows[8];
};

__global__ void transpose_convert_all(WPack p)
{
    __shared__ float t[32][33];
    const int z = blockIdx.z;
    const int rows = p.rows[z];
    const int by = blockIdx.y * 32;
    if (by >= rows) return;
    const float* in = p.src[z];
    __half* h = p.h[z];
    int bx = blockIdx.x * 32;
    int x = threadIdx.x, y = threadIdx.y;
    #pragma unroll
    for (int i = 0; i < 32; i += 8)
        t[y + i][x] = in[(size_t)(by + y + i) * DB + bx + x];
    __syncthreads();
    #pragma unroll
    for (int i = 0; i < 32; i += 8)
        h[(size_t)(bx + y + i) * rows + by + x] = __float2half_rn(t[x][y + i]);
}

// ---------------------------------------------------------------------------
// 16-bit transpose, batched over z.
// ---------------------------------------------------------------------------
__global__ void transpose16(const uint16_t* __restrict__ in,
                            uint16_t* __restrict__ outp, int rows, int cols)
{
    __shared__ uint16_t t[32][34];
    const size_t boff = (size_t)blockIdx.z * rows * cols;
    const uint16_t* ib = in + boff;
    uint16_t* ob = outp + boff;
    int bx = blockIdx.x * 32, by = blockIdx.y * 32;
    int x = threadIdx.x, y = threadIdx.y;
    #pragma unroll
    for (int i = 0; i < 32; i += 8)
        t[y + i][x] = ib[(size_t)(by + y + i) * cols + bx + x];
    __syncthreads();
    #pragma unroll
    for (int i = 0; i < 32; i += 8)
        ob[(size_t)(bx + y + i) * rows + by + x] = t[x][y + i];
}

// ---------------------------------------------------------------------------
// Row softmax over 2048 fp32 scores; writes fp16 P.
// ---------------------------------------------------------------------------
__global__ __launch_bounds__(256)
void softmax_kernel(const float* __restrict__ S, __half* __restrict__ Ph)
{
    const float4* row = (const float4*)(S + (size_t)blockIdx.x * SEQ);
    __half* ph = Ph + (size_t)blockIdx.x * SEQ;
    const int tid = threadIdx.x;
    __shared__ float red[256];

    float4 v0 = row[tid];
    float4 v1 = row[tid + 256];

    float m = fmaxf(fmaxf(fmaxf(v0.x, v0.y), fmaxf(v0.z, v0.w)),
                    fmaxf(fmaxf(v1.x, v1.y), fmaxf(v1.z, v1.w)));
    red[tid] = m;
    __syncthreads();
    #pragma unroll
    for (int s = 128; s > 0; s >>= 1) {
        if (tid < s) red[tid] = fmaxf(red[tid], red[tid + s]);
        __syncthreads();
    }
    m = red[0];
    __syncthreads();

    v0.x = __expf(v0.x - m); v0.y = __expf(v0.y - m);
    v0.z = __expf(v0.z - m); v0.w = __expf(v0.w - m);
    v1.x = __expf(v1.x - m); v1.y = __expf(v1.y - m);
    v1.z = __expf(v1.z - m); v1.w = __expf(v1.w - m);

    float sum = (v0.x + v0.y + v0.z + v0.w) + (v1.x + v1.y + v1.z + v1.w);
    red[tid] = sum;
    __syncthreads();
    #pragma unroll
    for (int s = 128; s > 0; s >>= 1) {
        if (tid < s) red[tid] += red[tid + s];
        __syncthreads();
    }
    float inv = 1.0f / red[0];

    v0.x *= inv; v0.y *= inv; v0.z *= inv; v0.w *= inv;
    v1.x *= inv; v1.y *= inv; v1.z *= inv; v1.w *= inv;

    uint2 uh;
    uh.x = pack2h(__float2half_rn(v0.x), __float2half_rn(v0.y));
    uh.y = pack2h(__float2half_rn(v0.z), __float2half_rn(v0.w));
    *(uint2*)&ph[tid * 4] = uh;
    uh.x = pack2h(__float2half_rn(v1.x), __float2half_rn(v1.y));
    uh.y = pack2h(__float2half_rn(v1.z), __float2half_rn(v1.w));
    *(uint2*)&ph[(tid + 256) * 4] = uh;
}

// ---------------------------------------------------------------------------
// Host-side plumbing
// ---------------------------------------------------------------------------
extern "C" void kernel_launch(void* const* d_in, const int* in_sizes, int n_in,
                              void* d_out, int out_size)
{
    const float* x_a   = (const float*)d_in[0];
    const float* x_b   = (const float*)d_in[1];
    const float* sa_wq = (const float*)d_in[2];
    const float* sa_bq = (const float*)d_in[3];
    const float* sa_wk = (const float*)d_in[4];
    const float* sa_bk = (const float*)d_in[5];
    const float* sa_wv = (const float*)d_in[6];
    const float* sa_bv = (const float*)d_in[7];
    const float* sa_wo = (const float*)d_in[8];
    const float* sa_bo = (const float*)d_in[9];
    const float* ca_wq = (const float*)d_in[10];
    const float* ca_bq = (const float*)d_in[11];
    const float* ca_wk = (const float*)d_in[12];
    const float* ca_bk = (const float*)d_in[13];
    const float* ca_wv = (const float*)d_in[14];
    const float* ca_bv = (const float*)d_in[15];
    const float* ca_wo = (const float*)d_in[16];
    const float* ca_bo = (const float*)d_in[17];
    float* out = (float*)d_out;

    cudaFuncSetAttribute(mma_gemm<true,  false, false, true>,
                         cudaFuncAttributeMaxDynamicSharedMemorySize, SMEM_DYN);
    cudaFuncSetAttribute(mma_gemm<false, false, true,  false>,
                         cudaFuncAttributeMaxDynamicSharedMemorySize, SMEM_DYN);
    cudaFuncSetAttribute(mma_gemm<false, false, false, true>,
                         cudaFuncAttributeMaxDynamicSharedMemorySize, SMEM_DYN);
    cudaFuncSetAttribute(mma_gemm<true,  true,  true,  true>,
                         cudaFuncAttributeMaxDynamicSharedMemorySize, SMEM_DYN);
    cudaFuncSetAttribute(mma_gemm<true,  true,  true,  false>,
                         cudaFuncAttributeMaxDynamicSharedMemorySize, SMEM_DYN);

    float *s, *xb2;
    __half *xbh, *xah, *qh, *kh, *vh, *vth, *ph, *x2h, *ath, *wth;
    cudaGetSymbolAddress((void**)&s,   g_s);
    cudaGetSymbolAddress((void**)&xb2, g_xb2);
    cudaGetSymbolAddress((void**)&xbh, g_xbh);
    cudaGetSymbolAddress((void**)&xah, g_xah);
    cudaGetSymbolAddress((void**)&qh,  g_qh);
    cudaGetSymbolAddress((void**)&kh,  g_kh);
    cudaGetSymbolAddress((void**)&vh,  g_vh);
    cudaGetSymbolAddress((void**)&vth, g_vth);
    cudaGetSymbolAddress((void**)&ph,  g_ph);
    cudaGetSymbolAddress((void**)&x2h, g_x2h);
    cudaGetSymbolAddress((void**)&ath, g_ath);
    cudaGetSymbolAddress((void**)&wth, g_wth);

    const int M = BATCH * SEQ;                  // 16384
    const size_t qkvS = (size_t)SEQ * DB;
    const size_t sS   = (size_t)SEQ * SEQ;
    const int WSZ = DB * DB;

    // ---- prep (3 launches) -------------------------------------------------
    {
        WPack p;
        const float* srcs[8] = {sa_wq, sa_wk, sa_wv, sa_wo, ca_wq, ca_wk, ca_wv, ca_wo};
        for (int i = 0; i < 8; i++) {
            p.src[i] = srcs[i];
            p.h[i] = wth + i * WSZ;
            p.rows[i] = (i == 4) ? DA : DB;
        }
        dim3 b(32, 8), g(DB / 32, DB / 32, 8);
        transpose_convert_all<<<g, b>>>(p);
        size_t nb4 = (size_t)M * DB / 4, na4 = (size_t)M * DA / 4;
        convert_kernel<<<(unsigned)((nb4 + 255) / 256), 256>>>(x_b, xbh, nb4);
        convert_kernel<<<(unsigned)((na4 + 255) / 256), 256>>>(x_a, xah, na4);
    }

    // ================= Self-attention on x_b ===============================
    {   // q,k,v projections (launch #5 = V proj for ncu)
        dim3 g(DB / 64, M / 128, 1);
        mma_gemm<true, false, false, true><<<g, 256, SMEM_DYN>>>(
            xbh, wth + 0 * WSZ, sa_bq, nullptr, nullptr, qh,
            M, DB, DB, 1.0f, 0, 0, 0);
        mma_gemm<true, false, false, true><<<g, 256, SMEM_DYN>>>(
            xbh, wth + 1 * WSZ, sa_bk, nullptr, nullptr, kh,
            M, DB, DB, 1.0f, 0, 0, 0);
        mma_gemm<true, false, false, true><<<g, 256, SMEM_DYN>>>(
            xbh, wth + 2 * WSZ, sa_bv, nullptr, nullptr, vh,
            M, DB, DB, 1.0f, 0, 0, 0);
    }
    {   // scores = Q @ K^T / 32
        dim3 g(SEQ / 64, SEQ / 128, BATCH);
        mma_gemm<false, false, true, false><<<g, 256, SMEM_DYN>>>(
            qh, kh, nullptr, nullptr, s, nullptr,
            SEQ, SEQ, DB, 1.0f / 32.0f, qkvS, qkvS, sS);
    }
    softmax_kernel<<<BATCH * SEQ, 256>>>(s, ph);
    {   // V^T per batch
        dim3 b(32, 8), g(DB / 32, SEQ / 32, BATCH);
        transpose16<<<g, b>>>((const uint16_t*)vh, (uint16_t*)vth, SEQ, DB);
    }
    {   // attn = P @ V
        dim3 g(DB / 64, SEQ / 128, BATCH);
        mma_gemm<false, false, false, true><<<g, 256, SMEM_DYN>>>(
            ph, vth, nullptr, nullptr, nullptr, ath,
            SEQ, DB, SEQ, 1.0f, sS, qkvS, qkvS);
    }
    {   // xb2 = x_b + attn @ Wo + bo
        dim3 g(DB / 64, M / 128, 1);
        mma_gemm<true, true, true, true><<<g, 256, SMEM_DYN>>>(
            ath, wth + 3 * WSZ, sa_bo, x_b, xb2, x2h,
            M, DB, DB, 1.0f, 0, 0, 0);
    }

    // ================= Cross-attention =====================================
    {
        dim3 g(DB / 64, M / 128, 1);
        mma_gemm<true, false, false, true><<<g, 256, SMEM_DYN>>>(
            xah, wth + 4 * WSZ, ca_bq, nullptr, nullptr, qh,
            M, DB, DA, 1.0f, 0, 0, 0);
        mma_gemm<true, false, false, true><<<g, 256, SMEM_DYN>>>(
            x2h, wth + 5 * WSZ, ca_bk, nullptr, nullptr, kh,
            M, DB, DB, 1.0f, 0, 0, 0);
        mma_gemm<true, false, false, true><<<g, 256, SMEM_DYN>>>(
            x2h, wth + 6 * WSZ, ca_bv, nullptr, nullptr, vh,
            M, DB, DB, 1.0f, 0, 0, 0);
    }
    {   // scores = Q @ K^T / sqrt(768)
        dim3 g(SEQ / 64, SEQ / 128, BATCH);
        mma_gemm<false, false, true, false><<<g, 256, SMEM_DYN>>>(
            qh, kh, nullptr, nullptr, s, nullptr,
            SEQ, SEQ, DB, 1.0f / sqrtf((float)DA), qkvS, qkvS, sS);
    }
    softmax_kernel<<<BATCH * SEQ, 256>>>(s, ph);
    {
        dim3 b(32, 8), g(DB / 32, SEQ / 32, BATCH);
        transpose16<<<g, b>>>((const uint16_t*)vh, (uint16_t*)vth, SEQ, DB);
    }
    {
        dim3 g(DB / 64, SEQ / 128, BATCH);
        mma_gemm<false, false, false, true><<<g, 256, SMEM_DYN>>>(
            ph, vth, nullptr, nullptr, nullptr, ath,
            SEQ, DB, SEQ, 1.0f, sS, qkvS, qkvS);
    }
    {   // out = xb2 + attn @ Wo + bo
        dim3 g(DB / 64, M / 128, 1);
        mma_gemm<true, true, true, false><<<g, 256, SMEM_DYN>>>(
            ath, wth + 7 * WSZ, ca_bo, xb2, out, nullptr,
            M, DB, DB, 1.0f, 0, 0, 0);
    }
}

// round 14
// speedup vs baseline: 3.4716x; 1.0514x over previous
#include <cuda_runtime.h>
#include <cuda_fp16.h>
#include <cstdint>
#include <math.h>

#define BATCH 8
#define SEQ   2048
#define DA    768
#define DB    1024

// ---------------- scratch (device globals; module-load allocation) ---------
__device__ float g_s   [BATCH * SEQ * SEQ];            // fp32 scores
__device__ float g_xb2 [BATCH * SEQ * DB];             // fp32 residual
__device__ __half g_xbh[BATCH * SEQ * DB];
__device__ __half g_xah[BATCH * SEQ * DA];
__device__ __half g_qh [BATCH * SEQ * DB];
__device__ __half g_kh [BATCH * SEQ * DB];
__device__ __half g_vh [BATCH * SEQ * DB];
__device__ __half g_vth[BATCH * SEQ * DB];
__device__ __half g_ph [BATCH * SEQ * SEQ];
__device__ __half g_x2h[BATCH * SEQ * DB];
__device__ __half g_ath[BATCH * SEQ * DB];
__device__ __half g_wth[8 * DB * DB];

// ---------------- helpers ---------------------------------------------------
__device__ __forceinline__ uint32_t pack2h(__half a, __half b) {
    __half2 t; t.x = a; t.y = b;
    return *(uint32_t*)&t;
}
__device__ __forceinline__ uint32_t smem_u32(const void* p) {
    uint32_t a;
    asm("{ .reg .u64 t; cvta.to.shared.u64 t, %1; cvt.u32.u64 %0, t; }"
        : "=r"(a) : "l"(p));
    return a;
}
__device__ __forceinline__ void cp16(uint32_t dst, const void* src) {
    asm volatile("cp.async.cg.shared.global [%0], [%1], 16;"
                 :: "r"(dst), "l"(src));
}
#define CP_COMMIT() asm volatile("cp.async.commit_group;")
#define CP_WAIT(n)  asm volatile("cp.async.wait_group %0;" :: "n"(n))

#define MMA_F16(acc, Af, Bf)                                                   \
    asm volatile(                                                              \
        "mma.sync.aligned.m16n8k16.row.col.f32.f16.f16.f32 "                   \
        "{%0,%1,%2,%3},{%4,%5,%6,%7},{%8,%9},{%0,%1,%2,%3};"                   \
        : "+f"((acc)[0]), "+f"((acc)[1]), "+f"((acc)[2]), "+f"((acc)[3])       \
        : "r"((Af)[0]), "r"((Af)[1]), "r"((Af)[2]), "r"((Af)[3]),              \
          "r"((Bf)[0]), "r"((Bf)[1]))

#define LDSM4(r0, r1, r2, r3, a)                                               \
    asm volatile("ldmatrix.sync.aligned.m8n8.x4.shared.b16 {%0,%1,%2,%3}, [%4];" \
        : "=r"(r0), "=r"(r1), "=r"(r2), "=r"(r3) : "r"(a))

// ---------------------------------------------------------------------------
// 1-pass fp16 GEMM via mma.sync (fp32 accum), 4-stage cp.async pipeline:
//   C = alpha * A @ B^T [+ bias] [+ res];  A:[M,K] fp16, B:[N,K] fp16.
//   CTA tile 128x64, warp tile 32x32 (8 warps as 4Mx2N), KC=32.
// SMEM stage: A 128 rows x 80B (64B payload) + B 64 rows x 80B = 15360B. x4.
// One __syncthreads per chunk: top-of-loop barrier (after wait_group 2) is
// also the WAR guard for stage (ch+3)%4 == (ch-1)%4 (consumed pre-barrier).
// ---------------------------------------------------------------------------
#define ROWB 80
#define OFF_B 10240
#define STAGE 15360
#define NSTAGE 4
#define SMEM_DYN (NSTAGE * STAGE)

template<bool HAS_BIAS, bool HAS_RES, bool WRITE_F32, bool WRITE_H>
__global__ __launch_bounds__(256, 3)
void mma_gemm(const __half* __restrict__ Ah, const __half* __restrict__ Bh,
              const float* __restrict__ bias, const float* __restrict__ res,
              float* __restrict__ C, __half* __restrict__ Ch,
              int M, int N, int K, float alpha,
              size_t sA, size_t sB, size_t sC)
{
    extern __shared__ char smem[];
    const uint32_t sb = smem_u32(smem);

    const int bz = blockIdx.z;
    Ah += (size_t)bz * sA;
    Bh += (size_t)bz * sB;
    const size_t cOff = (size_t)bz * sC;

    const int row0 = blockIdx.y * 128;
    const int col0 = blockIdx.x * 64;
    const int tid  = threadIdx.x;
    const int wid  = tid >> 5;
    const int lane = tid & 31;
    const int wm   = wid >> 1;          // 0..3  (M, 32 rows each)
    const int wn   = wid & 1;           // 0..1  (N, 32 cols each)
    const int lr   = lane >> 2;         // 0..7
    const int lc   = lane & 3;          // 0..3

    const int f0r = tid >> 2;           // 0..63
    const int f0c = tid & 3;            // 16B slot in 64B row payload
    const int g   = lane >> 3, ri = lane & 7;
    const int aR  = (g & 1) * 8 + ri;
    const int aC  = (g >> 1) * 16;
    const int bR  = (g >> 1) * 8 + ri;
    const int bC  = (g & 1) * 16;

    float acc[2][4][4];
    #pragma unroll
    for (int a = 0; a < 2; a++)
        #pragma unroll
        for (int b = 0; b < 4; b++)
            #pragma unroll
            for (int c = 0; c < 4; c++)
                acc[a][b][c] = 0.0f;

    const int nCh = K / 32;

    auto load_stage = [&](int st, int ch) {
        const uint32_t base = sb + st * STAGE;
        const uint32_t d = f0r * ROWB + f0c * 16;
        #pragma unroll
        for (int i = 0; i < 2; i++) {
            size_t oa = (size_t)(row0 + f0r + i * 64) * K + ch * 32 + f0c * 8;
            cp16(base + d + i * (64 * ROWB), Ah + oa);
        }
        size_t ob = (size_t)(col0 + f0r) * K + ch * 32 + f0c * 8;
        cp16(base + OFF_B + d, Bh + ob);
    };

    // prologue: 3 stages in flight
    load_stage(0, 0); CP_COMMIT();
    load_stage(1, 1); CP_COMMIT();
    if (nCh > 2) load_stage(2, 2);
    CP_COMMIT();

    for (int ch = 0; ch < nCh; ch++) {
        CP_WAIT(2);            // stage ch's group (and older) complete
        __syncthreads();       // data visible + all warps done with stage (ch-1)

        const uint32_t base = sb + (ch & 3) * STAGE;
        #pragma unroll
        for (int s = 0; s < 2; s++) {
            uint32_t Af[2][4], Bf[4][2];
            #pragma unroll
            for (int mt = 0; mt < 2; mt++) {
                uint32_t ar = base + (wm * 32 + mt * 16 + aR) * ROWB + s * 32 + aC;
                LDSM4(Af[mt][0], Af[mt][1], Af[mt][2], Af[mt][3], ar);
            }
            #pragma unroll
            for (int np = 0; np < 2; np++) {
                uint32_t br = base + OFF_B + (wn * 32 + np * 16 + bR) * ROWB + s * 32 + bC;
                LDSM4(Bf[2*np][0], Bf[2*np][1], Bf[2*np+1][0], Bf[2*np+1][1], br);
            }
            #pragma unroll
            for (int mt = 0; mt < 2; mt++)
                #pragma unroll
                for (int nt = 0; nt < 4; nt++)
                    MMA_F16(acc[mt][nt], Af[mt], Bf[nt]);
        }

        // refill stage (ch+3)%4 == (ch-1)%4 (safe: consumed before top barrier)
        if (ch + 3 < nCh) load_stage((ch + 3) & 3, ch + 3);
        CP_COMMIT();           // always commit (possibly empty) - keeps counts fixed
    }

    // ---- epilogue ----
    const float* __restrict__ R = HAS_RES ? (res + cOff) : nullptr;
    #pragma unroll
    for (int mt = 0; mt < 2; mt++) {
        #pragma unroll
        for (int nt = 0; nt < 4; nt++) {
            int r = row0 + wm * 32 + mt * 16 + lr;
            int c = col0 + wn * 32 + nt * 8 + lc * 2;
            float2 o0, o1;
            o0.x = acc[mt][nt][0] * alpha; o0.y = acc[mt][nt][1] * alpha;
            o1.x = acc[mt][nt][2] * alpha; o1.y = acc[mt][nt][3] * alpha;
            if (HAS_BIAS) {
                float2 bv = *(const float2*)&bias[c];
                o0.x += bv.x; o0.y += bv.y;
                o1.x += bv.x; o1.y += bv.y;
            }
            if (HAS_RES) {
                float2 r0 = *(const float2*)&R[(size_t)r * N + c];
                float2 r1 = *(const float2*)&R[(size_t)(r + 8) * N + c];
                o0.x += r0.x; o0.y += r0.y;
                o1.x += r1.x; o1.y += r1.y;
            }
            if (WRITE_F32) {
                *(float2*)&C[cOff + (size_t)r * N + c]       = o0;
                *(float2*)&C[cOff + (size_t)(r + 8) * N + c] = o1;
            }
            if (WRITE_H) {
                *(uint32_t*)&Ch[cOff + (size_t)r * N + c] =
                    pack2h(__float2half_rn(o0.x), __float2half_rn(o0.y));
                *(uint32_t*)&Ch[cOff + (size_t)(r + 8) * N + c] =
                    pack2h(__float2half_rn(o1.x), __float2half_rn(o1.y));
            }
        }
    }
}

// ---------------------------------------------------------------------------
// Elementwise convert fp32 -> fp16.
// ---------------------------------------------------------------------------
__global__ __launch_bounds__(256)
void convert_kernel(const float* __restrict__ in, __half* __restrict__ h, size_t n4)
{
    size_t i = (size_t)blockIdx.x * 256 + threadIdx.x;
    if (i >= n4) return;
    float4 v = ((const float4*)in)[i];
    uint2 uh;
    uh.x = pack2h(__float2half_rn(v.x), __float2half_rn(v.y));
    uh.y = pack2h(__float2half_rn(v.z), __float2half_rn(v.w));
    *(uint2*)&h[i * 4] = uh;
}

// ---------------------------------------------------------------------------
// All-weights transpose+convert in ONE launch (z = weight slot 0..7).
// ---------------------------------------------------------------------------
struct WPack {
    const float* src[8];
    __half* h[8];
    int rows[8];
};

__global__ void transpose_convert_all(WPack p)
{
    __shared__ float t[32][33];
    const int z = blockIdx.z;
    const int rows = p.rows[z];
    const int by = blockIdx.y * 32;
    if (by >= rows) return;
    const float* in = p.src[z];
    __half* h = p.h[z];
    int bx = blockIdx.x * 32;
    int x = threadIdx.x, y = threadIdx.y;
    #pragma unroll
    for (int i = 0; i < 32; i += 8)
        t[y + i][x] = in[(size_t)(by + y + i) * DB + bx + x];
    __syncthreads();
    #pragma unroll
    for (int i = 0; i < 32; i += 8)
        h[(size_t)(bx + y + i) * rows + by + x] = __float2half_rn(t[x][y + i]);
}

// ---------------------------------------------------------------------------
// 16-bit transpose, batched over z.
// ---------------------------------------------------------------------------
__global__ void transpose16(const uint16_t* __restrict__ in,
                            uint16_t* __restrict__ outp, int rows, int cols)
{
    __shared__ uint16_t t[32][34];
    const size_t boff = (size_t)blockIdx.z * rows * cols;
    const uint16_t* ib = in + boff;
    uint16_t* ob = outp + boff;
    int bx = blockIdx.x * 32, by = blockIdx.y * 32;
    int x = threadIdx.x, y = threadIdx.y;
    #pragma unroll
    for (int i = 0; i < 32; i += 8)
        t[y + i][x] = ib[(size_t)(by + y + i) * cols + bx + x];
    __syncthreads();
    #pragma unroll
    for (int i = 0; i < 32; i += 8)
        ob[(size_t)(bx + y + i) * rows + by + x] = t[x][y + i];
}

// ---------------------------------------------------------------------------
// Row softmax over 2048 fp32 scores; writes fp16 P.
// ---------------------------------------------------------------------------
__global__ __launch_bounds__(256)
void softmax_kernel(const float* __restrict__ S, __half* __restrict__ Ph)
{
    const float4* row = (const float4*)(S + (size_t)blockIdx.x * SEQ);
    __half* ph = Ph + (size_t)blockIdx.x * SEQ;
    const int tid = threadIdx.x;
    __shared__ float red[256];

    float4 v0 = row[tid];
    float4 v1 = row[tid + 256];

    float m = fmaxf(fmaxf(fmaxf(v0.x, v0.y), fmaxf(v0.z, v0.w)),
                    fmaxf(fmaxf(v1.x, v1.y), fmaxf(v1.z, v1.w)));
    red[tid] = m;
    __syncthreads();
    #pragma unroll
    for (int s = 128; s > 0; s >>= 1) {
        if (tid < s) red[tid] = fmaxf(red[tid], red[tid + s]);
        __syncthreads();
    }
    m = red[0];
    __syncthreads();

    v0.x = __expf(v0.x - m); v0.y = __expf(v0.y - m);
    v0.z = __expf(v0.z - m); v0.w = __expf(v0.w - m);
    v1.x = __expf(v1.x - m); v1.y = __expf(v1.y - m);
    v1.z = __expf(v1.z - m); v1.w = __expf(v1.w - m);

    float sum = (v0.x + v0.y + v0.z + v0.w) + (v1.x + v1.y + v1.z + v1.w);
    red[tid] = sum;
    __syncthreads();
    #pragma unroll
    for (int s = 128; s > 0; s >>= 1) {
        if (tid < s) red[tid] += red[tid + s];
        __syncthreads();
    }
    float inv = 1.0f / red[0];

    v0.x *= inv; v0.y *= inv; v0.z *= inv; v0.w *= inv;
    v1.x *= inv; v1.y *= inv; v1.z *= inv; v1.w *= inv;

    uint2 uh;
    uh.x = pack2h(__float2half_rn(v0.x), __float2half_rn(v0.y));
    uh.y = pack2h(__float2half_rn(v0.z), __float2half_rn(v0.w));
    *(uint2*)&ph[tid * 4] = uh;
    uh.x = pack2h(__float2half_rn(v1.x), __float2half_rn(v1.y));
    uh.y = pack2h(__float2half_rn(v1.z), __float2half_rn(v1.w));
    *(uint2*)&ph[(tid + 256) * 4] = uh;
}

// ---------------------------------------------------------------------------
// Host-side plumbing
// ---------------------------------------------------------------------------
extern "C" void kernel_launch(void* const* d_in, const int* in_sizes, int n_in,
                              void* d_out, int out_size)
{
    const float* x_a   = (const float*)d_in[0];
    const float* x_b   = (const float*)d_in[1];
    const float* sa_wq = (const float*)d_in[2];
    const float* sa_bq = (const float*)d_in[3];
    const float* sa_wk = (const float*)d_in[4];
    const float* sa_bk = (const float*)d_in[5];
    const float* sa_wv = (const float*)d_in[6];
    const float* sa_bv = (const float*)d_in[7];
    const float* sa_wo = (const float*)d_in[8];
    const float* sa_bo = (const float*)d_in[9];
    const float* ca_wq = (const float*)d_in[10];
    const float* ca_bq = (const float*)d_in[11];
    const float* ca_wk = (const float*)d_in[12];
    const float* ca_bk = (const float*)d_in[13];
    const float* ca_wv = (const float*)d_in[14];
    const float* ca_bv = (const float*)d_in[15];
    const float* ca_wo = (const float*)d_in[16];
    const float* ca_bo = (const float*)d_in[17];
    float* out = (float*)d_out;

    cudaFuncSetAttribute(mma_gemm<true,  false, false, true>,
                         cudaFuncAttributeMaxDynamicSharedMemorySize, SMEM_DYN);
    cudaFuncSetAttribute(mma_gemm<false, false, true,  false>,
                         cudaFuncAttributeMaxDynamicSharedMemorySize, SMEM_DYN);
    cudaFuncSetAttribute(mma_gemm<false, false, false, true>,
                         cudaFuncAttributeMaxDynamicSharedMemorySize, SMEM_DYN);
    cudaFuncSetAttribute(mma_gemm<true,  true,  true,  true>,
                         cudaFuncAttributeMaxDynamicSharedMemorySize, SMEM_DYN);
    cudaFuncSetAttribute(mma_gemm<true,  true,  true,  false>,
                         cudaFuncAttributeMaxDynamicSharedMemorySize, SMEM_DYN);

    float *s, *xb2;
    __half *xbh, *xah, *qh, *kh, *vh, *vth, *ph, *x2h, *ath, *wth;
    cudaGetSymbolAddress((void**)&s,   g_s);
    cudaGetSymbolAddress((void**)&xb2, g_xb2);
    cudaGetSymbolAddress((void**)&xbh, g_xbh);
    cudaGetSymbolAddress((void**)&xah, g_xah);
    cudaGetSymbolAddress((void**)&qh,  g_qh);
    cudaGetSymbolAddress((void**)&kh,  g_kh);
    cudaGetSymbolAddress((void**)&vh,  g_vh);
    cudaGetSymbolAddress((void**)&vth, g_vth);
    cudaGetSymbolAddress((void**)&ph,  g_ph);
    cudaGetSymbolAddress((void**)&x2h, g_x2h);
    cudaGetSymbolAddress((void**)&ath, g_ath);
    cudaGetSymbolAddress((void**)&wth, g_wth);

    const int M = BATCH * SEQ;                  // 16384
    const size_t qkvS = (size_t)SEQ * DB;
    const size_t sS   = (size_t)SEQ * SEQ;
    const int WSZ = DB * DB;

    // ---- prep (3 launches) -------------------------------------------------
    {
        WPack p;
        const float* srcs[8] = {sa_wq, sa_wk, sa_wv, sa_wo, ca_wq, ca_wk, ca_wv, ca_wo};
        for (int i = 0; i < 8; i++) {
            p.src[i] = srcs[i];
            p.h[i] = wth + i * WSZ;
            p.rows[i] = (i == 4) ? DA : DB;
        }
        dim3 b(32, 8), g(DB / 32, DB / 32, 8);
        transpose_convert_all<<<g, b>>>(p);
        size_t nb4 = (size_t)M * DB / 4, na4 = (size_t)M * DA / 4;
        convert_kernel<<<(unsigned)((nb4 + 255) / 256), 256>>>(x_b, xbh, nb4);
        convert_kernel<<<(unsigned)((na4 + 255) / 256), 256>>>(x_a, xah, na4);
    }

    // ================= Self-attention on x_b ===============================
    {   // q,k,v projections (launch #5 = V proj for ncu)
        dim3 g(DB / 64, M / 128, 1);
        mma_gemm<true, false, false, true><<<g, 256, SMEM_DYN>>>(
            xbh, wth + 0 * WSZ, sa_bq, nullptr, nullptr, qh,
            M, DB, DB, 1.0f, 0, 0, 0);
        mma_gemm<true, false, false, true><<<g, 256, SMEM_DYN>>>(
            xbh, wth + 1 * WSZ, sa_bk, nullptr, nullptr, kh,
            M, DB, DB, 1.0f, 0, 0, 0);
        mma_gemm<true, false, false, true><<<g, 256, SMEM_DYN>>>(
            xbh, wth + 2 * WSZ, sa_bv, nullptr, nullptr, vh,
            M, DB, DB, 1.0f, 0, 0, 0);
    }
    {   // scores = Q @ K^T / 32
        dim3 g(SEQ / 64, SEQ / 128, BATCH);
        mma_gemm<false, false, true, false><<<g, 256, SMEM_DYN>>>(
            qh, kh, nullptr, nullptr, s, nullptr,
            SEQ, SEQ, DB, 1.0f / 32.0f, qkvS, qkvS, sS);
    }
    softmax_kernel<<<BATCH * SEQ, 256>>>(s, ph);
    {   // V^T per batch
        dim3 b(32, 8), g(DB / 32, SEQ / 32, BATCH);
        transpose16<<<g, b>>>((const uint16_t*)vh, (uint16_t*)vth, SEQ, DB);
    }
    {   // attn = P @ V
        dim3 g(DB / 64, SEQ / 128, BATCH);
        mma_gemm<false, false, false, true><<<g, 256, SMEM_DYN>>>(
            ph, vth, nullptr, nullptr, nullptr, ath,
            SEQ, DB, SEQ, 1.0f, sS, qkvS, qkvS);
    }
    {   // xb2 = x_b + attn @ Wo + bo
        dim3 g(DB / 64, M / 128, 1);
        mma_gemm<true, true, true, true><<<g, 256, SMEM_DYN>>>(
            ath, wth + 3 * WSZ, sa_bo, x_b, xb2, x2h,
            M, DB, DB, 1.0f, 0, 0, 0);
    }

    // ================= Cross-attention =====================================
    {
        dim3 g(DB / 64, M / 128, 1);
        mma_gemm<true, false, false, true><<<g, 256, SMEM_DYN>>>(
            xah, wth + 4 * WSZ, ca_bq, nullptr, nullptr, qh,
            M, DB, DA, 1.0f, 0, 0, 0);
        mma_gemm<true, false, false, true><<<g, 256, SMEM_DYN>>>(
            x2h, wth + 5 * WSZ, ca_bk, nullptr, nullptr, kh,
            M, DB, DB, 1.0f, 0, 0, 0);
        mma_gemm<true, false, false, true><<<g, 256, SMEM_DYN>>>(
            x2h, wth + 6 * WSZ, ca_bv, nullptr, nullptr, vh,
            M, DB, DB, 1.0f, 0, 0, 0);
    }
    {   // scores = Q @ K^T / sqrt(768)
        dim3 g(SEQ / 64, SEQ / 128, BATCH);
        mma_gemm<false, false, true, false><<<g, 256, SMEM_DYN>>>(
            qh, kh, nullptr, nullptr, s, nullptr,
            SEQ, SEQ, DB, 1.0f / sqrtf((float)DA), qkvS, qkvS, sS);
    }
    softmax_kernel<<<BATCH * SEQ, 256>>>(s, ph);
    {
        dim3 b(32, 8), g(DB / 32, SEQ / 32, BATCH);
        transpose16<<<g, b>>>((const uint16_t*)vh, (uint16_t*)vth, SEQ, DB);
    }
    {
        dim3 g(DB / 64, SEQ / 128, BATCH);
        mma_gemm<false, false, false, true><<<g, 256, SMEM_DYN>>>(
            ph, vth, nullptr, nullptr, nullptr, ath,
            SEQ, DB, SEQ, 1.0f, sS, qkvS, qkvS);
    }
    {   // out = xb2 + attn @ Wo + bo
        dim3 g(DB / 64, M / 128, 1);
        mma_gemm<true, true, true, false><<<g, 256, SMEM_DYN>>>(
            ath, wth + 7 * WSZ, ca_bo, xb2, out, nullptr,
            M, DB, DB, 1.0f, 0, 0, 0);
    }
}

// round 15
// speedup vs baseline: 4.3196x; 1.2443x over previous
#include <cuda_runtime.h>
#include <cuda_fp16.h>
#include <cstdint>
#include <math.h>

#define BATCH 8
#define SEQ   2048
#define DA    768
#define DB    1024

// ---------------- scratch (device globals; module-load allocation) ---------
__device__ float g_s   [BATCH * SEQ * SEQ];            // fp32 scores
__device__ float g_xb2 [BATCH * SEQ * DB];             // fp32 residual
__device__ __half g_xbh[BATCH * SEQ * DB];
__device__ __half g_xah[BATCH * SEQ * DA];
__device__ __half g_qh [BATCH * SEQ * DB];
__device__ __half g_kh [BATCH * SEQ * DB];
__device__ __half g_vh [BATCH * SEQ * DB];
__device__ __half g_vth[BATCH * SEQ * DB];
__device__ __half g_ph [BATCH * SEQ * SEQ];
__device__ __half g_x2h[BATCH * SEQ * DB];
__device__ __half g_ath[BATCH * SEQ * DB];
__device__ __half g_wth[8 * DB * DB];

// ---------------- helpers ---------------------------------------------------
__device__ __forceinline__ uint32_t pack2h(__half a, __half b) {
    __half2 t; t.x = a; t.y = b;
    return *(uint32_t*)&t;
}
__device__ __forceinline__ uint32_t smem_u32(const void* p) {
    uint32_t a;
    asm("{ .reg .u64 t; cvta.to.shared.u64 t, %1; cvt.u32.u64 %0, t; }"
        : "=r"(a) : "l"(p));
    return a;
}
__device__ __forceinline__ void cp16(uint32_t dst, const void* src) {
    asm volatile("cp.async.cg.shared.global [%0], [%1], 16;"
                 :: "r"(dst), "l"(src));
}
#define CP_COMMIT() asm volatile("cp.async.commit_group;")
#define CP_WAIT(n)  asm volatile("cp.async.wait_group %0;" :: "n"(n))

#define MMA_F16(acc, Af, Bf)                                                   \
    asm volatile(                                                              \
        "mma.sync.aligned.m16n8k16.row.col.f32.f16.f16.f32 "                   \
        "{%0,%1,%2,%3},{%4,%5,%6,%7},{%8,%9},{%0,%1,%2,%3};"                   \
        : "+f"((acc)[0]), "+f"((acc)[1]), "+f"((acc)[2]), "+f"((acc)[3])       \
        : "r"((Af)[0]), "r"((Af)[1]), "r"((Af)[2]), "r"((Af)[3]),              \
          "r"((Bf)[0]), "r"((Bf)[1]))

#define LDSM4(r0, r1, r2, r3, a)                                               \
    asm volatile("ldmatrix.sync.aligned.m8n8.x4.shared.b16 {%0,%1,%2,%3}, [%4];" \
        : "=r"(r0), "=r"(r1), "=r"(r2), "=r"(r3) : "r"(a))

// ---------------------------------------------------------------------------
// 1-pass fp16 GEMM via mma.sync (fp32 accum), 4-stage cp.async pipeline:
//   C = alpha * A @ B^T [+ bias] [+ res];  A:[M,K] fp16, B:[N,K] fp16.
//   CTA tile 128x128, warp tile 64x32 (8 warps as 2Mx4N), KC=32.
//   Bigger warp tile cuts smem bytes/MMA ~2.2x vs 32x32 (smem-bound fix).
// SMEM stage: A 128 rows x 80B + B 128 rows x 80B = 20480B. x4 stages.
// One __syncthreads per chunk (top barrier doubles as WAR guard).
// ---------------------------------------------------------------------------
#define ROWB 80
#define OFF_B 10240
#define STAGE 20480
#define NSTAGE 4
#define SMEM_DYN (NSTAGE * STAGE)

template<bool HAS_BIAS, bool HAS_RES, bool WRITE_F32, bool WRITE_H>
__global__ __launch_bounds__(256, 2)
void mma_gemm(const __half* __restrict__ Ah, const __half* __restrict__ Bh,
              const float* __restrict__ bias, const float* __restrict__ res,
              float* __restrict__ C, __half* __restrict__ Ch,
              int M, int N, int K, float alpha,
              size_t sA, size_t sB, size_t sC)
{
    extern __shared__ char smem[];
    const uint32_t sb = smem_u32(smem);

    const int bz = blockIdx.z;
    Ah += (size_t)bz * sA;
    Bh += (size_t)bz * sB;
    const size_t cOff = (size_t)bz * sC;

    const int row0 = blockIdx.y * 128;
    const int col0 = blockIdx.x * 128;
    const int tid  = threadIdx.x;
    const int wid  = tid >> 5;
    const int lane = tid & 31;
    const int wm   = wid >> 2;          // 0..1  (M, 64 rows each)
    const int wn   = wid & 3;           // 0..3  (N, 32 cols each)
    const int lr   = lane >> 2;         // 0..7
    const int lc   = lane & 3;          // 0..3

    const int f0r = tid >> 2;           // 0..63
    const int f0c = tid & 3;            // 16B slot in 64B row payload
    const int g   = lane >> 3, ri = lane & 7;
    const int aR  = (g & 1) * 8 + ri;
    const int aC  = (g >> 1) * 16;
    const int bR  = (g >> 1) * 8 + ri;
    const int bC  = (g & 1) * 16;

    float acc[4][4][4];                 // [mt][nt][4] -> 64 regs
    #pragma unroll
    for (int a = 0; a < 4; a++)
        #pragma unroll
        for (int b = 0; b < 4; b++)
            #pragma unroll
            for (int c = 0; c < 4; c++)
                acc[a][b][c] = 0.0f;

    const int nCh = K / 32;

    auto load_stage = [&](int st, int ch) {
        const uint32_t base = sb + st * STAGE;
        const uint32_t d = f0r * ROWB + f0c * 16;
        #pragma unroll
        for (int i = 0; i < 2; i++) {
            size_t oa = (size_t)(row0 + f0r + i * 64) * K + ch * 32 + f0c * 8;
            size_t ob = (size_t)(col0 + f0r + i * 64) * K + ch * 32 + f0c * 8;
            cp16(base + d + i * (64 * ROWB), Ah + oa);
            cp16(base + OFF_B + d + i * (64 * ROWB), Bh + ob);
        }
    };

    // prologue: 3 stages in flight
    load_stage(0, 0); CP_COMMIT();
    load_stage(1, 1); CP_COMMIT();
    if (nCh > 2) load_stage(2, 2);
    CP_COMMIT();

    for (int ch = 0; ch < nCh; ch++) {
        CP_WAIT(2);            // stage ch's group (and older) complete
        __syncthreads();       // data visible + all warps done with stage (ch-1)

        const uint32_t base = sb + (ch & 3) * STAGE;
        #pragma unroll
        for (int s = 0; s < 2; s++) {
            uint32_t Af[4][4], Bf[4][2];
            #pragma unroll
            for (int mt = 0; mt < 4; mt++) {
                uint32_t ar = base + (wm * 64 + mt * 16 + aR) * ROWB + s * 32 + aC;
                LDSM4(Af[mt][0], Af[mt][1], Af[mt][2], Af[mt][3], ar);
            }
            #pragma unroll
            for (int np = 0; np < 2; np++) {
                uint32_t br = base + OFF_B + (wn * 32 + np * 16 + bR) * ROWB + s * 32 + bC;
                LDSM4(Bf[2*np][0], Bf[2*np][1], Bf[2*np+1][0], Bf[2*np+1][1], br);
            }
            #pragma unroll
            for (int mt = 0; mt < 4; mt++)
                #pragma unroll
                for (int nt = 0; nt < 4; nt++)
                    MMA_F16(acc[mt][nt], Af[mt], Bf[nt]);
        }

        // refill stage (ch+3)%4 == (ch-1)%4 (consumed before top barrier)
        if (ch + 3 < nCh) load_stage((ch + 3) & 3, ch + 3);
        CP_COMMIT();           // always commit (possibly empty) - keeps counts fixed
    }

    // ---- epilogue ----
    const float* __restrict__ R = HAS_RES ? (res + cOff) : nullptr;
    #pragma unroll
    for (int mt = 0; mt < 4; mt++) {
        #pragma unroll
        for (int nt = 0; nt < 4; nt++) {
            int r = row0 + wm * 64 + mt * 16 + lr;
            int c = col0 + wn * 32 + nt * 8 + lc * 2;
            float2 o0, o1;
            o0.x = acc[mt][nt][0] * alpha; o0.y = acc[mt][nt][1] * alpha;
            o1.x = acc[mt][nt][2] * alpha; o1.y = acc[mt][nt][3] * alpha;
            if (HAS_BIAS) {
                float2 bv = *(const float2*)&bias[c];
                o0.x += bv.x; o0.y += bv.y;
                o1.x += bv.x; o1.y += bv.y;
            }
            if (HAS_RES) {
                float2 r0 = *(const float2*)&R[(size_t)r * N + c];
                float2 r1 = *(const float2*)&R[(size_t)(r + 8) * N + c];
                o0.x += r0.x; o0.y += r0.y;
                o1.x += r1.x; o1.y += r1.y;
            }
            if (WRITE_F32) {
                *(float2*)&C[cOff + (size_t)r * N + c]       = o0;
                *(float2*)&C[cOff + (size_t)(r + 8) * N + c] = o1;
            }
            if (WRITE_H) {
                *(uint32_t*)&Ch[cOff + (size_t)r * N + c] =
                    pack2h(__float2half_rn(o0.x), __float2half_rn(o0.y));
                *(uint32_t*)&Ch[cOff + (size_t)(r + 8) * N + c] =
                    pack2h(__float2half_rn(o1.x), __float2half_rn(o1.y));
            }
        }
    }
}

// ---------------------------------------------------------------------------
// Elementwise convert fp32 -> fp16.
// ---------------------------------------------------------------------------
__global__ __launch_bounds__(256)
void convert_kernel(const float* __restrict__ in, __half* __restrict__ h, size_t n4)
{
    size_t i = (size_t)blockIdx.x * 256 + threadIdx.x;
    if (i >= n4) return;
    float4 v = ((const float4*)in)[i];
    uint2 uh;
    uh.x = pack2h(__float2half_rn(v.x), __float2half_rn(v.y));
    uh.y = pack2h(__float2half_rn(v.z), __float2half_rn(v.w));
    *(uint2*)&h[i * 4] = uh;
}

// ---------------------------------------------------------------------------
// All-weights transpose+convert in ONE launch (z = weight slot 0..7).
// ---------------------------------------------------------------------------
struct WPack {
    const float* src[8];
    __half* h[8];
    int rows[8];
};

__global__ void transpose_convert_all(WPack p)
{
    __shared__ float t[32][33];
    const int z = blockIdx.z;
    const int rows = p.rows[z];
    const int by = blockIdx.y * 32;
    if (by >= rows) return;
    const float* in = p.src[z];
    __half* h = p.h[z];
    int bx = blockIdx.x * 32;
    int x = threadIdx.x, y = threadIdx.y;
    #pragma unroll
    for (int i = 0; i < 32; i += 8)
        t[y + i][x] = in[(size_t)(by + y + i) * DB + bx + x];
    __syncthreads();
    #pragma unroll
    for (int i = 0; i < 32; i += 8)
        h[(size_t)(bx + y + i) * rows + by + x] = __float2half_rn(t[x][y + i]);
}

// ---------------------------------------------------------------------------
// 16-bit transpose, batched over z.
// ---------------------------------------------------------------------------
__global__ void transpose16(const uint16_t* __restrict__ in,
                            uint16_t* __restrict__ outp, int rows, int cols)
{
    __shared__ uint16_t t[32][34];
    const size_t boff = (size_t)blockIdx.z * rows * cols;
    const uint16_t* ib = in + boff;
    uint16_t* ob = outp + boff;
    int bx = blockIdx.x * 32, by = blockIdx.y * 32;
    int x = threadIdx.x, y = threadIdx.y;
    #pragma unroll
    for (int i = 0; i < 32; i += 8)
        t[y + i][x] = ib[(size_t)(by + y + i) * cols + bx + x];
    __syncthreads();
    #pragma unroll
    for (int i = 0; i < 32; i += 8)
        ob[(size_t)(bx + y + i) * rows + by + x] = t[x][y + i];
}

// ---------------------------------------------------------------------------
// Row softmax over 2048 fp32 scores; writes fp16 P.
// ---------------------------------------------------------------------------
__global__ __launch_bounds__(256)
void softmax_kernel(const float* __restrict__ S, __half* __restrict__ Ph)
{
    const float4* row = (const float4*)(S + (size_t)blockIdx.x * SEQ);
    __half* ph = Ph + (size_t)blockIdx.x * SEQ;
    const int tid = threadIdx.x;
    __shared__ float red[256];

    float4 v0 = row[tid];
    float4 v1 = row[tid + 256];

    float m = fmaxf(fmaxf(fmaxf(v0.x, v0.y), fmaxf(v0.z, v0.w)),
                    fmaxf(fmaxf(v1.x, v1.y), fmaxf(v1.z, v1.w)));
    red[tid] = m;
    __syncthreads();
    #pragma unroll
    for (int s = 128; s > 0; s >>= 1) {
        if (tid < s) red[tid] = fmaxf(red[tid], red[tid + s]);
        __syncthreads();
    }
    m = red[0];
    __syncthreads();

    v0.x = __expf(v0.x - m); v0.y = __expf(v0.y - m);
    v0.z = __expf(v0.z - m); v0.w = __expf(v0.w - m);
    v1.x = __expf(v1.x - m); v1.y = __expf(v1.y - m);
    v1.z = __expf(v1.z - m); v1.w = __expf(v1.w - m);

    float sum = (v0.x + v0.y + v0.z + v0.w) + (v1.x + v1.y + v1.z + v1.w);
    red[tid] = sum;
    __syncthreads();
    #pragma unroll
    for (int s = 128; s > 0; s >>= 1) {
        if (tid < s) red[tid] += red[tid + s];
        __syncthreads();
    }
    float inv = 1.0f / red[0];

    v0.x *= inv; v0.y *= inv; v0.z *= inv; v0.w *= inv;
    v1.x *= inv; v1.y *= inv; v1.z *= inv; v1.w *= inv;

    uint2 uh;
    uh.x = pack2h(__float2half_rn(v0.x), __float2half_rn(v0.y));
    uh.y = pack2h(__float2half_rn(v0.z), __float2half_rn(v0.w));
    *(uint2*)&ph[tid * 4] = uh;
    uh.x = pack2h(__float2half_rn(v1.x), __float2half_rn(v1.y));
    uh.y = pack2h(__float2half_rn(v1.z), __float2half_rn(v1.w));
    *(uint2*)&ph[(tid + 256) * 4] = uh;
}

// ---------------------------------------------------------------------------
// Host-side plumbing
// ---------------------------------------------------------------------------
extern "C" void kernel_launch(void* const* d_in, const int* in_sizes, int n_in,
                              void* d_out, int out_size)
{
    const float* x_a   = (const float*)d_in[0];
    const float* x_b   = (const float*)d_in[1];
    const float* sa_wq = (const float*)d_in[2];
    const float* sa_bq = (const float*)d_in[3];
    const float* sa_wk = (const float*)d_in[4];
    const float* sa_bk = (const float*)d_in[5];
    const float* sa_wv = (const float*)d_in[6];
    const float* sa_bv = (const float*)d_in[7];
    const float* sa_wo = (const float*)d_in[8];
    const float* sa_bo = (const float*)d_in[9];
    const float* ca_wq = (const float*)d_in[10];
    const float* ca_bq = (const float*)d_in[11];
    const float* ca_wk = (const float*)d_in[12];
    const float* ca_bk = (const float*)d_in[13];
    const float* ca_wv = (const float*)d_in[14];
    const float* ca_bv = (const float*)d_in[15];
    const float* ca_wo = (const float*)d_in[16];
    const float* ca_bo = (const float*)d_in[17];
    float* out = (float*)d_out;

    cudaFuncSetAttribute(mma_gemm<true,  false, false, true>,
                         cudaFuncAttributeMaxDynamicSharedMemorySize, SMEM_DYN);
    cudaFuncSetAttribute(mma_gemm<false, false, true,  false>,
                         cudaFuncAttributeMaxDynamicSharedMemorySize, SMEM_DYN);
    cudaFuncSetAttribute(mma_gemm<false, false, false, true>,
                         cudaFuncAttributeMaxDynamicSharedMemorySize, SMEM_DYN);
    cudaFuncSetAttribute(mma_gemm<true,  true,  true,  true>,
                         cudaFuncAttributeMaxDynamicSharedMemorySize, SMEM_DYN);
    cudaFuncSetAttribute(mma_gemm<true,  true,  true,  false>,
                         cudaFuncAttributeMaxDynamicSharedMemorySize, SMEM_DYN);

    float *s, *xb2;
    __half *xbh, *xah, *qh, *kh, *vh, *vth, *ph, *x2h, *ath, *wth;
    cudaGetSymbolAddress((void**)&s,   g_s);
    cudaGetSymbolAddress((void**)&xb2, g_xb2);
    cudaGetSymbolAddress((void**)&xbh, g_xbh);
    cudaGetSymbolAddress((void**)&xah, g_xah);
    cudaGetSymbolAddress((void**)&qh,  g_qh);
    cudaGetSymbolAddress((void**)&kh,  g_kh);
    cudaGetSymbolAddress((void**)&vh,  g_vh);
    cudaGetSymbolAddress((void**)&vth, g_vth);
    cudaGetSymbolAddress((void**)&ph,  g_ph);
    cudaGetSymbolAddress((void**)&x2h, g_x2h);
    cudaGetSymbolAddress((void**)&ath, g_ath);
    cudaGetSymbolAddress((void**)&wth, g_wth);

    const int M = BATCH * SEQ;                  // 16384
    const size_t qkvS = (size_t)SEQ * DB;
    const size_t sS   = (size_t)SEQ * SEQ;
    const int WSZ = DB * DB;

    // ---- prep (3 launches) -------------------------------------------------
    {
        WPack p;
        const float* srcs[8] = {sa_wq, sa_wk, sa_wv, sa_wo, ca_wq, ca_wk, ca_wv, ca_wo};
        for (int i = 0; i < 8; i++) {
            p.src[i] = srcs[i];
            p.h[i] = wth + i * WSZ;
            p.rows[i] = (i == 4) ? DA : DB;
        }
        dim3 b(32, 8), g(DB / 32, DB / 32, 8);
        transpose_convert_all<<<g, b>>>(p);
        size_t nb4 = (size_t)M * DB / 4, na4 = (size_t)M * DA / 4;
        convert_kernel<<<(unsigned)((nb4 + 255) / 256), 256>>>(x_b, xbh, nb4);
        convert_kernel<<<(unsigned)((na4 + 255) / 256), 256>>>(x_a, xah, na4);
    }

    // ================= Self-attention on x_b ===============================
    {   // q,k,v projections (launch #5 = V proj for ncu)
        dim3 g(DB / 128, M / 128, 1);
        mma_gemm<true, false, false, true><<<g, 256, SMEM_DYN>>>(
            xbh, wth + 0 * WSZ, sa_bq, nullptr, nullptr, qh,
            M, DB, DB, 1.0f, 0, 0, 0);
        mma_gemm<true, false, false, true><<<g, 256, SMEM_DYN>>>(
            xbh, wth + 1 * WSZ, sa_bk, nullptr, nullptr, kh,
            M, DB, DB, 1.0f, 0, 0, 0);
        mma_gemm<true, false, false, true><<<g, 256, SMEM_DYN>>>(
            xbh, wth + 2 * WSZ, sa_bv, nullptr, nullptr, vh,
            M, DB, DB, 1.0f, 0, 0, 0);
    }
    {   // scores = Q @ K^T / 32
        dim3 g(SEQ / 128, SEQ / 128, BATCH);
        mma_gemm<false, false, true, false><<<g, 256, SMEM_DYN>>>(
            qh, kh, nullptr, nullptr, s, nullptr,
            SEQ, SEQ, DB, 1.0f / 32.0f, qkvS, qkvS, sS);
    }
    softmax_kernel<<<BATCH * SEQ, 256>>>(s, ph);
    {   // V^T per batch
        dim3 b(32, 8), g(DB / 32, SEQ / 32, BATCH);
        transpose16<<<g, b>>>((const uint16_t*)vh, (uint16_t*)vth, SEQ, DB);
    }
    {   // attn = P @ V
        dim3 g(DB / 128, SEQ / 128, BATCH);
        mma_gemm<false, false, false, true><<<g, 256, SMEM_DYN>>>(
            ph, vth, nullptr, nullptr, nullptr, ath,
            SEQ, DB, SEQ, 1.0f, sS, qkvS, qkvS);
    }
    {   // xb2 = x_b + attn @ Wo + bo
        dim3 g(DB / 128, M / 128, 1);
        mma_gemm<true, true, true, true><<<g, 256, SMEM_DYN>>>(
            ath, wth + 3 * WSZ, sa_bo, x_b, xb2, x2h,
            M, DB, DB, 1.0f, 0, 0, 0);
    }

    // ================= Cross-attention =====================================
    {
        dim3 g(DB / 128, M / 128, 1);
        mma_gemm<true, false, false, true><<<g, 256, SMEM_DYN>>>(
            xah, wth + 4 * WSZ, ca_bq, nullptr, nullptr, qh,
            M, DB, DA, 1.0f, 0, 0, 0);
        mma_gemm<true, false, false, true><<<g, 256, SMEM_DYN>>>(
            x2h, wth + 5 * WSZ, ca_bk, nullptr, nullptr, kh,
            M, DB, DB, 1.0f, 0, 0, 0);
        mma_gemm<true, false, false, true><<<g, 256, SMEM_DYN>>>(
            x2h, wth + 6 * WSZ, ca_bv, nullptr, nullptr, vh,
            M, DB, DB, 1.0f, 0, 0, 0);
    }
    {   // scores = Q @ K^T / sqrt(768)
        dim3 g(SEQ / 128, SEQ / 128, BATCH);
        mma_gemm<false, false, true, false><<<g, 256, SMEM_DYN>>>(
            qh, kh, nullptr, nullptr, s, nullptr,
            SEQ, SEQ, DB, 1.0f / sqrtf((float)DA), qkvS, qkvS, sS);
    }
    softmax_kernel<<<BATCH * SEQ, 256>>>(s, ph);
    {
        dim3 b(32, 8), g(DB / 32, SEQ / 32, BATCH);
        transpose16<<<g, b>>>((const uint16_t*)vh, (uint16_t*)vth, SEQ, DB);
    }
    {
        dim3 g(DB / 128, SEQ / 128, BATCH);
        mma_gemm<false, false, false, true><<<g, 256, SMEM_DYN>>>(
            ph, vth, nullptr, nullptr, nullptr, ath,
            SEQ, DB, SEQ, 1.0f, sS, qkvS, qkvS);
    }
    {   // out = xb2 + attn @ Wo + bo
        dim3 g(DB / 128, M / 128, 1);
        mma_gemm<true, true, true, false><<<g, 256, SMEM_DYN>>>(
            ath, wth + 7 * WSZ, ca_bo, xb2, out, nullptr,
            M, DB, DB, 1.0f, 0, 0, 0);
    }
}